// round 10
// baseline (speedup 1.0000x reference)
#include <cuda_runtime.h>
#include <math_constants.h>

#define Bc 8
#define Lc 4096
#define Hc 8
#define Dc 64
#define Sc 45
#define Uc 45
#define BHc (Bc*Hc)
#define NSPLIT 8
#define KSPLIT (Lc/NSPLIT)
#define TK 64
#define NCH 64
#define CHL (Lc/NCH)
#define KR 512                 // keys per k-range (smem tile)
#define NKR (Lc/KR)            // 8 k-ranges
#define ETOT (Lc*Sc)
#define K1_SMEM (KR*Dc*4)      // 128 KB
#define FIXSCALE 16777216.0f

// ---- scratch ----
__device__ int   g_idx[ETOT];
__device__ int   g_cnt[NKR*Lc];
__device__ int   g_qofs[NKR*Lc];
__device__ unsigned int g_pack[ETOT];   // (q<<9)|kl, sorted by (krange,q,s)
__device__ unsigned int g_Mmax[BHc*Lc];
__device__ unsigned long long g_Msum[BHc*Lc];
__device__ int   g_top[BHc*Uc];
__device__ float g_pm[BHc*Uc*NSPLIT];
__device__ float g_pl[BHc*Uc*NSPLIT];
__device__ float g_pacc[BHc*Uc*NSPLIT*Dc];
__device__ float g_ps[Bc*NCH*Hc*Dc];

// ============================================================
// b_prep: dtype detect + convert + per-krange counts + zero accums
// ============================================================
__global__ void __launch_bounds__(256) b_prep(const void* __restrict__ raw)
{
    __shared__ unsigned int red[256];
    const unsigned int* p = (const unsigned int*)raw;
    unsigned int acc = 0;
    for (int j = 1 + 2*threadIdx.x; j < 1024; j += 512) acc |= p[j];
    red[threadIdx.x] = acc;
    __syncthreads();
    for (int o = 128; o > 0; o >>= 1) {
        if (threadIdx.x < o) red[threadIdx.x] |= red[threadIdx.x + o];
        __syncthreads();
    }
    int mode64 = (red[0] == 0u) ? 1 : 0;

    int nthr = gridDim.x * 256;
    int gt = blockIdx.x*256 + threadIdx.x;
    for (int i = gt; i < BHc*Lc; i += nthr) {
        g_Mmax[i] = 0u;
        g_Msum[i] = 0ull;
    }

    int q = gt;
    if (q >= Lc) return;
    int c[NKR];
    #pragma unroll
    for (int i = 0; i < NKR; i++) c[i] = 0;
    for (int s = 0; s < Sc; s++) {
        int v;
        if (mode64) v = (int)((const long long*)raw)[q*Sc + s];
        else        v = ((const int*)raw)[q*Sc + s];
        g_idx[q*Sc + s] = v;
        c[v >> 9]++;
    }
    #pragma unroll
    for (int i = 0; i < NKR; i++) g_cnt[i*Lc + q] = c[i];
}

// ============================================================
// b_scan: block per krange; exclusive scan over q + global base
// ============================================================
__global__ void __launch_bounds__(512) b_scan()
{
    __shared__ int part[512];
    __shared__ int sbase[512];
    int kr = blockIdx.x, t = threadIdx.x;
    int bacc = 0;
    for (int i = t; i < kr*Lc; i += 512) bacc += g_cnt[i];
    sbase[t] = bacc;
    __syncthreads();
    for (int o = 256; o > 0; o >>= 1) {
        if (t < o) sbase[t] += sbase[t + o];
        __syncthreads();
    }
    int base = sbase[0];

    int v[8], pre[8], sum = 0;
    for (int j = 0; j < 8; j++) {
        v[j] = g_cnt[kr*Lc + t*8 + j];
        pre[j] = sum; sum += v[j];
    }
    part[t] = sum;
    __syncthreads();
    for (int off = 1; off < 512; off <<= 1) {
        int x = (t >= off) ? part[t-off] : 0;
        __syncthreads();
        part[t] += x;
        __syncthreads();
    }
    int excl = part[t] - sum;
    for (int j = 0; j < 8; j++)
        g_qofs[kr*Lc + t*8 + j] = base + excl + pre[j];
}

// ============================================================
// b_fill: thread per q, deterministic sequential cursors.
// ============================================================
__global__ void __launch_bounds__(256) b_fill()
{
    int q = blockIdx.x * 256 + threadIdx.x;
    if (q >= Lc) return;
    int cur[NKR];
    #pragma unroll
    for (int i = 0; i < NKR; i++) cur[i] = g_qofs[i*Lc + q];
    unsigned int qb = (unsigned int)q << 9;
    for (int s = 0; s < Sc; s++) {
        int k = g_idx[q*Sc + s];
        int kr = k >> 9;
        g_pack[cur[kr]++] = qb | ((unsigned int)k & 511u);
    }
}

// ============================================================
// K1: key-tiled scoring, KR=512. Per-q-run register accumulation
// (runs avg 5.6 entries) -> fewer Q reloads + fewer atomics.
// ============================================================
__global__ void __launch_bounds__(1024) k1_scores(
    const float* __restrict__ Q, const float* __restrict__ K)
{
    extern __shared__ float4 Ks4[];   // [KR][16] = 128KB
    int kr = blockIdx.x, bh = blockIdx.y;
    int b = bh >> 3, h = bh & 7;
    int tid = threadIdx.x;
    const float4* Q4 = (const float4*)Q;
    const float4* K4 = (const float4*)K;

    int kb = kr * KR;
    for (int i = tid; i < KR*16; i += 1024) {
        int row = i >> 4, part = i & 15;
        Ks4[i] = K4[(((b*Lc + kb + row)*Hc + h) << 4) + part];
    }
    __syncthreads();

    int start = g_qofs[kr*Lc];
    int end   = (kr == NKR-1) ? ETOT : g_qofs[(kr+1)*Lc];
    int n = end - start;
    int gid = tid >> 3, t = tid & 7;
    int per = (n + 127) >> 7;
    int e0 = gid * per;
    int e1 = min(n, e0 + per);
    const int qrow_base = ((b*Lc*Hc + h) << 4) + 2*t;
    const int mbase = bh * Lc;
    const int t2 = 2*t;

    int qcur = -1;
    float runMax = -CUDART_INF_F, runSum = 0.f;
    float4 qa = make_float4(0.f,0.f,0.f,0.f), qb = qa;

    #pragma unroll 4
    for (int e = e0; e < e1; e++) {
        unsigned int en = g_pack[start + e];
        int q = (int)(en >> 9);
        if (q != qcur) {
            if (t == 0 && qcur >= 0) {
                unsigned int u = __float_as_uint(runMax);
                unsigned int key = (u & 0x80000000u) ? ~u : (u | 0x80000000u);
                atomicMax(&g_Mmax[mbase + qcur], key);
                atomicAdd(&g_Msum[mbase + qcur],
                          (unsigned long long)(long long)__float2ll_rn(runSum * FIXSCALE));
            }
            qcur = q;
            runMax = -CUDART_INF_F; runSum = 0.f;
            const float4* qp = &Q4[qrow_base + (q << 7)];
            qa = __ldg(qp); qb = __ldg(qp + 1);
        }
        int ki = (int)((en & 511u) << 4) + t2;
        float4 ka = Ks4[ki], kc = Ks4[ki + 1];
        float d = qa.x*ka.x + qa.y*ka.y + qa.z*ka.z + qa.w*ka.w
                + qb.x*kc.x + qb.y*kc.y + qb.z*kc.z + qb.w*kc.w;
        d += __shfl_xor_sync(0xffffffffu, d, 1, 8);
        d += __shfl_xor_sync(0xffffffffu, d, 2, 8);
        d += __shfl_xor_sync(0xffffffffu, d, 4, 8);
        runMax = fmaxf(runMax, d);
        runSum += d;
    }
    if (t == 0 && qcur >= 0) {
        unsigned int u = __float_as_uint(runMax);
        unsigned int key = (u & 0x80000000u) ? ~u : (u | 0x80000000u);
        atomicMax(&g_Mmax[mbase + qcur], key);
        atomicAdd(&g_Msum[mbase + qcur],
                  (unsigned long long)(long long)__float2ll_rn(runSum * FIXSCALE));
    }
}

// ============================================================
// K2: M from (max,sum) + radix top-45 with PARALLEL suffix scan
// ============================================================
__global__ void __launch_bounds__(256) k2_topk()
{
    __shared__ unsigned int keys[Lc];
    __shared__ int hist[256];
    __shared__ int sel_bin, sel_rem, cnt;
    int bh = blockIdx.x, tid = threadIdx.x;
    for (int i = tid; i < Lc; i += 256) {
        unsigned int mk = g_Mmax[bh*Lc + i];
        unsigned int uu = (mk & 0x80000000u) ? (mk & 0x7FFFFFFFu) : ~mk;
        float mmax = __uint_as_float(uu);
        long long sll = (long long)g_Msum[bh*Lc + i];
        float M = mmax - (float)sll * (1.0f / (FIXSCALE * (float)Lc));
        unsigned int u = __float_as_uint(M);
        keys[i] = (u & 0x80000000u) ? ~u : (u | 0x80000000u);
    }
    if (tid == 0) cnt = 0;
    __syncthreads();
    unsigned int prefix = 0; int need = Uc;
    for (int shift = 24; shift >= 0; shift -= 8) {
        hist[tid] = 0;
        __syncthreads();
        for (int i = tid; i < Lc; i += 256) {
            unsigned int k = keys[i];
            if (shift == 24 || (k >> (shift+8)) == prefix)
                atomicAdd(&hist[(k >> shift) & 255], 1);
        }
        __syncthreads();
        // parallel suffix scan: hist[t] := sum_{b>=t} hist[b]
        for (int off = 1; off < 256; off <<= 1) {
            int v = (tid + off < 256) ? hist[tid + off] : 0;
            __syncthreads();
            hist[tid] += v;
            __syncthreads();
        }
        int S  = hist[tid];
        int Sn = (tid < 255) ? hist[tid + 1] : 0;
        if (S >= need && Sn < need) { sel_bin = tid; sel_rem = need - Sn; }
        __syncthreads();
        prefix = (prefix << 8) | (unsigned int)sel_bin;
        need = sel_rem;
        __syncthreads();
    }
    for (int i = tid; i < Lc; i += 256) {
        if (keys[i] > prefix) { int p = atomicAdd(&cnt, 1); g_top[bh*Uc + p] = i; }
    }
    __syncthreads();
    for (int i = tid; i < Lc; i += 256) {
        if (keys[i] == prefix) {
            int p = atomicAdd(&cnt, 1);
            if (p < Uc) g_top[bh*Uc + p] = i;
        }
    }
}

// ============================================================
// K3: flash-style attention for the 45 selected queries (split-KV x8)
// ============================================================
__global__ void __launch_bounds__(512) k3_attn(
    const float* __restrict__ Q, const float* __restrict__ K,
    const float* __restrict__ V)
{
    __shared__ __align__(16) float Qs[Uc][Dc];
    __shared__ int   qpos_s[Uc];
    __shared__ float Kt[Dc][TK+1];
    __shared__ __align__(16) float Vt[TK][Dc];
    int split = blockIdx.x, bh = blockIdx.y;
    int b = bh >> 3, h = bh & 7;
    int tid = threadIdx.x, lane = tid & 31, w = tid >> 5;

    if (tid < Uc) qpos_s[tid] = g_top[bh*Uc + tid];
    __syncthreads();
    for (int i = tid; i < Uc*Dc; i += 512) {
        int u = i >> 6, d = i & 63;
        int qp = qpos_s[u];
        Qs[u][d] = Q[(((b*Lc + qp)*Hc + h) << 6) + d] * 0.125f;
    }
    __syncthreads();

    int maxqp = 0;
    for (int u = 0; u < Uc; u++) maxqp = max(maxqp, qpos_s[u]);
    int kb0 = split * KSPLIT;
    int ntiles = 0;
    if (maxqp >= kb0) {
        int nn = (maxqp - kb0) / TK + 1;
        ntiles = nn < (KSPLIT/TK) ? nn : (KSPLIT/TK);
    }

    float m[3], lsum[3], acc0[3], acc1[3];
    #pragma unroll
    for (int j = 0; j < 3; j++) { m[j] = -CUDART_INF_F; lsum[j]=0.f; acc0[j]=0.f; acc1[j]=0.f; }

    const float4* K4 = (const float4*)K;
    const float4* V4 = (const float4*)V;

    for (int tile = 0; tile < ntiles; tile++) {
        int kb = kb0 + tile * TK;
        for (int i = tid; i < TK*16; i += 512) {
            int k = i >> 4, d4 = i & 15;
            int gbase = (((b*Lc + kb + k)*Hc + h) << 4) + d4;
            float4 kv = K4[gbase];
            int d = d4 * 4;
            Kt[d][k] = kv.x; Kt[d+1][k] = kv.y; Kt[d+2][k] = kv.z; Kt[d+3][k] = kv.w;
            ((float4*)&Vt[k][0])[d4] = V4[gbase];
        }
        __syncthreads();
        #pragma unroll
        for (int j = 0; j < 3; j++) {
            int u = w*3 + j;
            if (u >= Uc) continue;
            int qp = qpos_s[u];
            if (qp < kb) continue;
            int nk = min(TK, qp - kb + 1);
            float s0 = 0.f, s1 = 0.f;
            #pragma unroll 8
            for (int d = 0; d < Dc; d++) {
                float qd = Qs[u][d];
                s0 += qd * Kt[d][lane];
                s1 += qd * Kt[d][lane+32];
            }
            if (lane >= nk)      s0 = -CUDART_INF_F;
            if (lane + 32 >= nk) s1 = -CUDART_INF_F;
            float tm = fmaxf(s0, s1);
            #pragma unroll
            for (int o = 16; o > 0; o >>= 1) tm = fmaxf(tm, __shfl_xor_sync(0xffffffffu, tm, o));
            float newm = fmaxf(m[j], tm);
            float p0 = __expf(s0 - newm);
            float p1 = __expf(s1 - newm);
            float ps = p0 + p1;
            #pragma unroll
            for (int o = 16; o > 0; o >>= 1) ps += __shfl_xor_sync(0xffffffffu, ps, o);
            float c = __expf(m[j] - newm);
            lsum[j] = lsum[j]*c + ps;
            m[j] = newm;
            acc0[j] *= c; acc1[j] *= c;
            for (int k = 0; k < nk; k++) {
                float pk = __shfl_sync(0xffffffffu, (k < 32) ? p0 : p1, k & 31);
                acc0[j] += pk * Vt[k][lane];
                acc1[j] += pk * Vt[k][lane+32];
            }
        }
        __syncthreads();
    }

    #pragma unroll
    for (int j = 0; j < 3; j++) {
        int u = w*3 + j;
        if (u >= Uc) continue;
        int base = (bh*Uc + u)*NSPLIT + split;
        if (qpos_s[u] < kb0) {
            if (lane == 0) { g_pm[base] = -CUDART_INF_F; g_pl[base] = 0.f; }
            g_pacc[base*Dc + lane] = 0.f;
            g_pacc[base*Dc + lane + 32] = 0.f;
        } else {
            if (lane == 0) { g_pm[base] = m[j]; g_pl[base] = lsum[j]; }
            g_pacc[base*Dc + lane] = acc0[j];
            g_pacc[base*Dc + lane + 32] = acc1[j];
        }
    }
}

// ============================================================
// K4a: per-chunk partial sums. K4c: prefix (self-computed) + cumsum.
// ============================================================
__global__ void __launch_bounds__(512) k4a_partials(const float* __restrict__ V)
{
    int b = blockIdx.x, ch = blockIdx.y, tid = threadIdx.x;
    float s = 0.f;
    int base = (b*Lc + ch*CHL) * (Hc*Dc) + tid;
    #pragma unroll 4
    for (int l = 0; l < CHL; l++) s += V[base + l*(Hc*Dc)];
    g_ps[(b*NCH + ch)*(Hc*Dc) + tid] = s;
}

__global__ void __launch_bounds__(512) k4c_cumsum(const float* __restrict__ V,
                                                  float* __restrict__ out)
{
    int b = blockIdx.x, ch = blockIdx.y, tid = threadIdx.x;
    float acc = 0.f;
    for (int i = 0; i < ch; i++)                   // same order as serial prefix
        acc += g_ps[(b*NCH + i)*(Hc*Dc) + tid];
    int base = (b*Lc + ch*CHL) * (Hc*Dc) + tid;
    #pragma unroll 4
    for (int l = 0; l < CHL; l++) {
        acc += V[base + l*(Hc*Dc)];
        out[base + l*(Hc*Dc)] = acc;
    }
}

// K5: combine split-KV partials and scatter into output
__global__ void __launch_bounds__(64) k5_combine_scatter(float* __restrict__ out)
{
    int u = blockIdx.x, bh = blockIdx.y, d = threadIdx.x;
    int b = bh >> 3, h = bh & 7;
    int base = (bh*Uc + u)*NSPLIT;
    float pm[NSPLIT], pl[NSPLIT];
    float M = -CUDART_INF_F;
    #pragma unroll
    for (int s = 0; s < NSPLIT; s++) {
        pm[s] = g_pm[base+s]; pl[s] = g_pl[base+s];
        M = fmaxf(M, pm[s]);
    }
    float Ls = 0.f, r = 0.f;
    #pragma unroll
    for (int s = 0; s < NSPLIT; s++) {
        float e = __expf(pm[s] - M);
        Ls += pl[s] * e;
        r  += g_pacc[(base+s)*Dc + d] * e;
    }
    int qp = g_top[bh*Uc + u];
    out[(((b*Lc + qp)*Hc + h) << 6) + d] = r / Ls;
}

// ============================================================
extern "C" void kernel_launch(void* const* d_in, const int* in_sizes, int n_in,
                              void* d_out, int out_size)
{
    const float* Q = (const float*)d_in[0];
    const float* K = (const float*)d_in[1];
    const float* V = (const float*)d_in[2];
    const void*  IDXRAW = d_in[3];
    float* out = (float*)d_out;

    cudaFuncSetAttribute(k1_scores, cudaFuncAttributeMaxDynamicSharedMemorySize, K1_SMEM);

    b_prep<<<64, 256>>>(IDXRAW);                      // 1
    b_scan<<<NKR, 512>>>();                           // 2
    b_fill<<<(Lc + 255)/256, 256>>>();                // 3
    k1_scores<<<dim3(NKR, BHc), 1024, K1_SMEM>>>(Q, K);  // 4 <- profiled
    k2_topk<<<BHc, 256>>>();                          // 5
    k3_attn<<<dim3(NSPLIT, BHc), 512>>>(Q, K, V);     // 6
    k4a_partials<<<dim3(Bc, NCH), Hc*Dc>>>(V);        // 7
    k4c_cumsum<<<dim3(Bc, NCH), Hc*Dc>>>(V, out);     // 8
    k5_combine_scatter<<<dim3(Uc, BHc), Dc>>>(out);   // 9
}

// round 11
// speedup vs baseline: 1.0753x; 1.0753x over previous
#include <cuda_runtime.h>
#include <math_constants.h>

#define Bc 8
#define Lc 4096
#define Hc 8
#define Dc 64
#define Sc 45
#define Uc 45
#define BHc (Bc*Hc)
#define NSPLIT 8
#define KSPLIT (Lc/NSPLIT)
#define TK 64
#define NCH 64
#define CHL (Lc/NCH)
#define KR 256
#define NKR (Lc/KR)            // 16
#define ETOT (Lc*Sc)
#define K1_SMEM (KR*Dc*4)      // 64 KB
#define FIXSCALE 16777216.0f

// ---- scratch ----
__device__ int   g_idx[ETOT];
__device__ int   g_cnt[NKR*Lc];
__device__ int   g_qofs[NKR*Lc];
__device__ unsigned int g_pack[ETOT];   // (q<<8)|kl, sorted by (krange,q,s)
__device__ unsigned int g_Mmax[BHc*Lc];
__device__ unsigned long long g_Msum[BHc*Lc];
__device__ int   g_top[BHc*Uc];
__device__ float g_pm[BHc*Uc*NSPLIT];
__device__ float g_pl[BHc*Uc*NSPLIT];
__device__ float g_pacc[BHc*Uc*NSPLIT*Dc];
__device__ float g_ps[Bc*NCH*Hc*Dc];

// ============================================================
// b_prep: dtype detect + convert + per-krange counts + zero accums
// ============================================================
__global__ void __launch_bounds__(256) b_prep(const void* __restrict__ raw)
{
    __shared__ unsigned int red[256];
    const unsigned int* p = (const unsigned int*)raw;
    unsigned int acc = 0;
    for (int j = 1 + 2*threadIdx.x; j < 1024; j += 512) acc |= p[j];
    red[threadIdx.x] = acc;
    __syncthreads();
    for (int o = 128; o > 0; o >>= 1) {
        if (threadIdx.x < o) red[threadIdx.x] |= red[threadIdx.x + o];
        __syncthreads();
    }
    int mode64 = (red[0] == 0u) ? 1 : 0;

    int nthr = gridDim.x * 256;
    int gt = blockIdx.x*256 + threadIdx.x;
    for (int i = gt; i < BHc*Lc; i += nthr) {
        g_Mmax[i] = 0u;
        g_Msum[i] = 0ull;
    }

    int q = gt;
    if (q >= Lc) return;
    int c[NKR];
    #pragma unroll
    for (int i = 0; i < NKR; i++) c[i] = 0;
    for (int s = 0; s < Sc; s++) {
        int v;
        if (mode64) v = (int)((const long long*)raw)[q*Sc + s];
        else        v = ((const int*)raw)[q*Sc + s];
        g_idx[q*Sc + s] = v;
        c[v >> 8]++;
    }
    #pragma unroll
    for (int i = 0; i < NKR; i++) g_cnt[i*Lc + q] = c[i];
}

// ============================================================
// b_scan: block per krange; exclusive scan over q + global base
// ============================================================
__global__ void __launch_bounds__(512) b_scan()
{
    __shared__ int part[512];
    __shared__ int sbase[512];
    int kr = blockIdx.x, t = threadIdx.x;
    int bacc = 0;
    for (int i = t; i < kr*Lc; i += 512) bacc += g_cnt[i];
    sbase[t] = bacc;
    __syncthreads();
    for (int o = 256; o > 0; o >>= 1) {
        if (t < o) sbase[t] += sbase[t + o];
        __syncthreads();
    }
    int base = sbase[0];

    int v[8], pre[8], sum = 0;
    for (int j = 0; j < 8; j++) {
        v[j] = g_cnt[kr*Lc + t*8 + j];
        pre[j] = sum; sum += v[j];
    }
    part[t] = sum;
    __syncthreads();
    for (int off = 1; off < 512; off <<= 1) {
        int x = (t >= off) ? part[t-off] : 0;
        __syncthreads();
        part[t] += x;
        __syncthreads();
    }
    int excl = part[t] - sum;
    for (int j = 0; j < 8; j++)
        g_qofs[kr*Lc + t*8 + j] = base + excl + pre[j];
}

// ============================================================
// b_fill: thread per q, deterministic sequential cursors.
// ============================================================
__global__ void __launch_bounds__(256) b_fill()
{
    int q = blockIdx.x * 256 + threadIdx.x;
    if (q >= Lc) return;
    int cur[NKR];
    #pragma unroll
    for (int i = 0; i < NKR; i++) cur[i] = g_qofs[i*Lc + q];
    unsigned int qb = (unsigned int)q << 8;
    for (int s = 0; s < Sc; s++) {
        int k = g_idx[q*Sc + s];
        int kr = k >> 8;
        g_pack[cur[kr]++] = qb | ((unsigned int)k & 255u);
    }
}

// ============================================================
// K1: key-tiled scoring, 4-deep software pipeline with
// unconditional Q prefetch (MLP=8) + per-run atomics.
// ============================================================
#define K1_FLUSH() do { \
    if (t == 0 && qcur >= 0) { \
        unsigned int u_ = __float_as_uint(runMax); \
        unsigned int key_ = (u_ & 0x80000000u) ? ~u_ : (u_ | 0x80000000u); \
        atomicMax(&g_Mmax[mbase + qcur], key_); \
        atomicAdd(&g_Msum[mbase + qcur], \
                  (unsigned long long)(long long)__float2ll_rn(runSum * FIXSCALE)); \
    } } while (0)

#define K1_ACCUM(qq, dd) do { \
    if ((qq) != qcur) { K1_FLUSH(); qcur = (qq); runMax = -CUDART_INF_F; runSum = 0.f; } \
    runMax = fmaxf(runMax, (dd)); runSum += (dd); } while (0)

__global__ void __launch_bounds__(512, 2) k1_scores(
    const float* __restrict__ Q, const float* __restrict__ K)
{
    extern __shared__ float4 Ks4[];   // [KR][16] = 64KB
    int kr = blockIdx.x, bh = blockIdx.y;
    int b = bh >> 3, h = bh & 7;
    int tid = threadIdx.x;
    const float4* Q4 = (const float4*)Q;
    const float4* K4 = (const float4*)K;

    int kb = kr * KR;
    for (int i = tid; i < KR*16; i += 512) {
        int row = i >> 4, part = i & 15;
        Ks4[i] = K4[(((b*Lc + kb + row)*Hc + h) << 4) + part];
    }
    __syncthreads();

    int start = g_qofs[kr*Lc];
    int end   = (kr == NKR-1) ? ETOT : g_qofs[(kr+1)*Lc];
    int n = end - start;
    int gid = tid >> 3, t = tid & 7;
    int per = (n + 63) >> 6;
    int e0 = gid * per;
    int e1 = min(n, e0 + per);
    const int qrow_base = ((b*Lc*Hc + h) << 4) + 2*t;
    const int mbase = bh * Lc;
    const int t2 = 2*t;
    const unsigned int* __restrict__ pk = g_pack + start;

    int qcur = -1;
    float runMax = -CUDART_INF_F, runSum = 0.f;

    int e = e0;
    for (; e + 4 <= e1; e += 4) {
        unsigned int en0 = pk[e], en1 = pk[e+1], en2 = pk[e+2], en3 = pk[e+3];
        int q0 = (int)(en0 >> 8), q1 = (int)(en1 >> 8);
        int q2 = (int)(en2 >> 8), q3 = (int)(en3 >> 8);
        const float4* P0 = &Q4[qrow_base + (q0 << 7)];
        const float4* P1 = &Q4[qrow_base + (q1 << 7)];
        const float4* P2 = &Q4[qrow_base + (q2 << 7)];
        const float4* P3 = &Q4[qrow_base + (q3 << 7)];
        float4 a0 = __ldg(P0), b0 = __ldg(P0+1);
        float4 a1 = __ldg(P1), b1 = __ldg(P1+1);
        float4 a2 = __ldg(P2), b2 = __ldg(P2+1);
        float4 a3 = __ldg(P3), b3 = __ldg(P3+1);
        int i0 = (int)((en0 & 255u) << 4) + t2;
        int i1 = (int)((en1 & 255u) << 4) + t2;
        int i2 = (int)((en2 & 255u) << 4) + t2;
        int i3 = (int)((en3 & 255u) << 4) + t2;
        float4 x0 = Ks4[i0], y0 = Ks4[i0+1];
        float4 x1 = Ks4[i1], y1 = Ks4[i1+1];
        float4 x2 = Ks4[i2], y2 = Ks4[i2+1];
        float4 x3 = Ks4[i3], y3 = Ks4[i3+1];
        float d0 = a0.x*x0.x + a0.y*x0.y + a0.z*x0.z + a0.w*x0.w
                 + b0.x*y0.x + b0.y*y0.y + b0.z*y0.z + b0.w*y0.w;
        float d1 = a1.x*x1.x + a1.y*x1.y + a1.z*x1.z + a1.w*x1.w
                 + b1.x*y1.x + b1.y*y1.y + b1.z*y1.z + b1.w*y1.w;
        float d2 = a2.x*x2.x + a2.y*x2.y + a2.z*x2.z + a2.w*x2.w
                 + b2.x*y2.x + b2.y*y2.y + b2.z*y2.z + b2.w*y2.w;
        float d3 = a3.x*x3.x + a3.y*x3.y + a3.z*x3.z + a3.w*x3.w
                 + b3.x*y3.x + b3.y*y3.y + b3.z*y3.z + b3.w*y3.w;
        d0 += __shfl_xor_sync(0xffffffffu, d0, 1, 8);
        d1 += __shfl_xor_sync(0xffffffffu, d1, 1, 8);
        d2 += __shfl_xor_sync(0xffffffffu, d2, 1, 8);
        d3 += __shfl_xor_sync(0xffffffffu, d3, 1, 8);
        d0 += __shfl_xor_sync(0xffffffffu, d0, 2, 8);
        d1 += __shfl_xor_sync(0xffffffffu, d1, 2, 8);
        d2 += __shfl_xor_sync(0xffffffffu, d2, 2, 8);
        d3 += __shfl_xor_sync(0xffffffffu, d3, 2, 8);
        d0 += __shfl_xor_sync(0xffffffffu, d0, 4, 8);
        d1 += __shfl_xor_sync(0xffffffffu, d1, 4, 8);
        d2 += __shfl_xor_sync(0xffffffffu, d2, 4, 8);
        d3 += __shfl_xor_sync(0xffffffffu, d3, 4, 8);
        K1_ACCUM(q0, d0);
        K1_ACCUM(q1, d1);
        K1_ACCUM(q2, d2);
        K1_ACCUM(q3, d3);
    }
    for (; e < e1; e++) {
        unsigned int en = pk[e];
        int q = (int)(en >> 8);
        const float4* P = &Q4[qrow_base + (q << 7)];
        float4 qa = __ldg(P), qb = __ldg(P + 1);
        int ki = (int)((en & 255u) << 4) + t2;
        float4 ka = Ks4[ki], kc = Ks4[ki + 1];
        float d = qa.x*ka.x + qa.y*ka.y + qa.z*ka.z + qa.w*ka.w
                + qb.x*kc.x + qb.y*kc.y + qb.z*kc.z + qb.w*kc.w;
        d += __shfl_xor_sync(0xffffffffu, d, 1, 8);
        d += __shfl_xor_sync(0xffffffffu, d, 2, 8);
        d += __shfl_xor_sync(0xffffffffu, d, 4, 8);
        K1_ACCUM(q, d);
    }
    K1_FLUSH();
}

// ============================================================
// K2: M from (max,sum) + radix top-45, 512 threads
// ============================================================
__global__ void __launch_bounds__(512) k2_topk()
{
    __shared__ unsigned int keys[Lc];
    __shared__ int hist[256];
    __shared__ int sel_bin, sel_rem, cnt;
    int bh = blockIdx.x, tid = threadIdx.x;
    for (int i = tid; i < Lc; i += 512) {
        unsigned int mk = g_Mmax[bh*Lc + i];
        unsigned int uu = (mk & 0x80000000u) ? (mk & 0x7FFFFFFFu) : ~mk;
        float mmax = __uint_as_float(uu);
        long long sll = (long long)g_Msum[bh*Lc + i];
        float M = mmax - (float)sll * (1.0f / (FIXSCALE * (float)Lc));
        unsigned int u = __float_as_uint(M);
        keys[i] = (u & 0x80000000u) ? ~u : (u | 0x80000000u);
    }
    if (tid == 0) cnt = 0;
    __syncthreads();
    unsigned int prefix = 0; int need = Uc;
    for (int shift = 24; shift >= 0; shift -= 8) {
        if (tid < 256) hist[tid] = 0;
        __syncthreads();
        for (int i = tid; i < Lc; i += 512) {
            unsigned int k = keys[i];
            if (shift == 24 || (k >> (shift+8)) == prefix)
                atomicAdd(&hist[(k >> shift) & 255], 1);
        }
        __syncthreads();
        for (int off = 1; off < 256; off <<= 1) {
            int v = (tid < 256 && tid + off < 256) ? hist[tid + off] : 0;
            __syncthreads();
            if (tid < 256) hist[tid] += v;
            __syncthreads();
        }
        if (tid < 256) {
            int S  = hist[tid];
            int Sn = (tid < 255) ? hist[tid + 1] : 0;
            if (S >= need && Sn < need) { sel_bin = tid; sel_rem = need - Sn; }
        }
        __syncthreads();
        prefix = (prefix << 8) | (unsigned int)sel_bin;
        need = sel_rem;
        __syncthreads();
    }
    for (int i = tid; i < Lc; i += 512) {
        if (keys[i] > prefix) { int p = atomicAdd(&cnt, 1); g_top[bh*Uc + p] = i; }
    }
    __syncthreads();
    for (int i = tid; i < Lc; i += 512) {
        if (keys[i] == prefix) {
            int p = atomicAdd(&cnt, 1);
            if (p < Uc) g_top[bh*Uc + p] = i;
        }
    }
}

// ============================================================
// K3: flash attention, joint 3-u per warp (shared LDS/shfl)
// ============================================================
__global__ void __launch_bounds__(512) k3_attn(
    const float* __restrict__ Q, const float* __restrict__ K,
    const float* __restrict__ V)
{
    __shared__ float Qs[Uc][Dc];
    __shared__ int   qpos_s[Uc];
    __shared__ float Kt[Dc][TK+1];
    __shared__ __align__(16) float Vt[TK][Dc];
    int split = blockIdx.x, bh = blockIdx.y;
    int b = bh >> 3, h = bh & 7;
    int tid = threadIdx.x, lane = tid & 31, w = tid >> 5;

    if (tid < Uc) qpos_s[tid] = g_top[bh*Uc + tid];
    __syncthreads();
    for (int i = tid; i < Uc*Dc; i += 512) {
        int u = i >> 6, d = i & 63;
        int qp = qpos_s[u];
        Qs[u][d] = Q[(((b*Lc + qp)*Hc + h) << 6) + d] * 0.125f;
    }
    __syncthreads();

    int maxqp = 0;
    for (int u = 0; u < Uc; u++) maxqp = max(maxqp, qpos_s[u]);
    int kb0 = split * KSPLIT;
    int ntiles = 0;
    if (maxqp >= kb0) {
        int nn = (maxqp - kb0) / TK + 1;
        ntiles = nn < (KSPLIT/TK) ? nn : (KSPLIT/TK);
    }

    int u0 = w*3;
    int qp[3]; bool val[3];
    #pragma unroll
    for (int j = 0; j < 3; j++) {
        int u = u0 + j;
        val[j] = (u < Uc);
        qp[j] = val[j] ? qpos_s[u] : -0x40000000;
    }
    int wqmax = max(qp[0], max(qp[1], qp[2]));

    float m[3], lsum[3], acc0[3], acc1[3];
    #pragma unroll
    for (int j = 0; j < 3; j++) { m[j] = -CUDART_INF_F; lsum[j]=0.f; acc0[j]=0.f; acc1[j]=0.f; }

    const float4* K4 = (const float4*)K;
    const float4* V4 = (const float4*)V;

    for (int tile = 0; tile < ntiles; tile++) {
        int kb = kb0 + tile * TK;
        for (int i = tid; i < TK*16; i += 512) {
            int k = i >> 4, d4 = i & 15;
            int gbase = (((b*Lc + kb + k)*Hc + h) << 4) + d4;
            float4 kv = K4[gbase];
            int d = d4 * 4;
            Kt[d][k] = kv.x; Kt[d+1][k] = kv.y; Kt[d+2][k] = kv.z; Kt[d+3][k] = kv.w;
            ((float4*)&Vt[k][0])[d4] = V4[gbase];
        }
        __syncthreads();
        if (wqmax >= kb) {
            float s0[3] = {0.f,0.f,0.f}, s1[3] = {0.f,0.f,0.f};
            #pragma unroll 8
            for (int d = 0; d < Dc; d++) {
                float kt0 = Kt[d][lane], kt1 = Kt[d][lane+32];
                #pragma unroll
                for (int j = 0; j < 3; j++) {
                    float qd = Qs[min(u0+j, Uc-1)][d];
                    s0[j] += qd * kt0;
                    s1[j] += qd * kt1;
                }
            }
            float p0[3], p1[3];
            int kmax = 0;
            #pragma unroll
            for (int j = 0; j < 3; j++) {
                if (val[j] && qp[j] >= kb) {
                    int nk = min(TK, qp[j] - kb + 1);
                    kmax = max(kmax, nk);
                    float t0 = (lane      < nk) ? s0[j] : -CUDART_INF_F;
                    float t1 = (lane + 32 < nk) ? s1[j] : -CUDART_INF_F;
                    float tm = fmaxf(t0, t1);
                    #pragma unroll
                    for (int o = 16; o > 0; o >>= 1) tm = fmaxf(tm, __shfl_xor_sync(0xffffffffu, tm, o));
                    float newm = fmaxf(m[j], tm);
                    p0[j] = __expf(t0 - newm);
                    p1[j] = __expf(t1 - newm);
                    float ps = p0[j] + p1[j];
                    #pragma unroll
                    for (int o = 16; o > 0; o >>= 1) ps += __shfl_xor_sync(0xffffffffu, ps, o);
                    float cf = __expf(m[j] - newm);
                    lsum[j] = lsum[j]*cf + ps;
                    m[j] = newm;
                    acc0[j] *= cf; acc1[j] *= cf;
                } else { p0[j] = 0.f; p1[j] = 0.f; }
            }
            int k1end = min(kmax, 32);
            for (int k = 0; k < k1end; k++) {
                float vt0 = Vt[k][lane], vt1 = Vt[k][lane+32];
                #pragma unroll
                for (int j = 0; j < 3; j++) {
                    float pk = __shfl_sync(0xffffffffu, p0[j], k);
                    acc0[j] += pk * vt0;
                    acc1[j] += pk * vt1;
                }
            }
            for (int k = 32; k < kmax; k++) {
                float vt0 = Vt[k][lane], vt1 = Vt[k][lane+32];
                #pragma unroll
                for (int j = 0; j < 3; j++) {
                    float pk = __shfl_sync(0xffffffffu, p1[j], k - 32);
                    acc0[j] += pk * vt0;
                    acc1[j] += pk * vt1;
                }
            }
        }
        __syncthreads();
    }

    #pragma unroll
    for (int j = 0; j < 3; j++) {
        if (!val[j]) continue;
        int base = ((bh*Uc + u0 + j))*NSPLIT + split;
        if (qp[j] < kb0) {
            if (lane == 0) { g_pm[base] = -CUDART_INF_F; g_pl[base] = 0.f; }
            g_pacc[base*Dc + lane] = 0.f;
            g_pacc[base*Dc + lane + 32] = 0.f;
        } else {
            if (lane == 0) { g_pm[base] = m[j]; g_pl[base] = lsum[j]; }
            g_pacc[base*Dc + lane] = acc0[j];
            g_pacc[base*Dc + lane + 32] = acc1[j];
        }
    }
}

// ============================================================
// K4a: per-chunk partial sums. K4c: self-computed prefix + cumsum.
// ============================================================
__global__ void __launch_bounds__(512) k4a_partials(const float* __restrict__ V)
{
    int b = blockIdx.x, ch = blockIdx.y, tid = threadIdx.x;
    float s = 0.f;
    int base = (b*Lc + ch*CHL) * (Hc*Dc) + tid;
    #pragma unroll 4
    for (int l = 0; l < CHL; l++) s += V[base + l*(Hc*Dc)];
    g_ps[(b*NCH + ch)*(Hc*Dc) + tid] = s;
}

__global__ void __launch_bounds__(512) k4c_cumsum(const float* __restrict__ V,
                                                  float* __restrict__ out)
{
    int b = blockIdx.x, ch = blockIdx.y, tid = threadIdx.x;
    float acc = 0.f;
    for (int i = 0; i < ch; i++)
        acc += g_ps[(b*NCH + i)*(Hc*Dc) + tid];
    int base = (b*Lc + ch*CHL) * (Hc*Dc) + tid;
    #pragma unroll 4
    for (int l = 0; l < CHL; l++) {
        acc += V[base + l*(Hc*Dc)];
        out[base + l*(Hc*Dc)] = acc;
    }
}

// K5: combine split-KV partials and scatter into output
__global__ void __launch_bounds__(64) k5_combine_scatter(float* __restrict__ out)
{
    int u = blockIdx.x, bh = blockIdx.y, d = threadIdx.x;
    int b = bh >> 3, h = bh & 7;
    int base = (bh*Uc + u)*NSPLIT;
    float pm[NSPLIT], pl[NSPLIT];
    float M = -CUDART_INF_F;
    #pragma unroll
    for (int s = 0; s < NSPLIT; s++) {
        pm[s] = g_pm[base+s]; pl[s] = g_pl[base+s];
        M = fmaxf(M, pm[s]);
    }
    float Ls = 0.f, r = 0.f;
    #pragma unroll
    for (int s = 0; s < NSPLIT; s++) {
        float e = __expf(pm[s] - M);
        Ls += pl[s] * e;
        r  += g_pacc[(base+s)*Dc + d] * e;
    }
    int qp = g_top[bh*Uc + u];
    out[(((b*Lc + qp)*Hc + h) << 6) + d] = r / Ls;
}

// ============================================================
extern "C" void kernel_launch(void* const* d_in, const int* in_sizes, int n_in,
                              void* d_out, int out_size)
{
    const float* Q = (const float*)d_in[0];
    const float* K = (const float*)d_in[1];
    const float* V = (const float*)d_in[2];
    const void*  IDXRAW = d_in[3];
    float* out = (float*)d_out;

    cudaFuncSetAttribute(k1_scores, cudaFuncAttributeMaxDynamicSharedMemorySize, K1_SMEM);

    b_prep<<<64, 256>>>(IDXRAW);                      // 1
    b_scan<<<NKR, 512>>>();                           // 2
    b_fill<<<(Lc + 255)/256, 256>>>();                // 3
    k1_scores<<<dim3(NKR, BHc), 512, K1_SMEM>>>(Q, K);   // 4 <- profiled
    k2_topk<<<BHc, 512>>>();                          // 5
    k3_attn<<<dim3(NSPLIT, BHc), 512>>>(Q, K, V);     // 6
    k4a_partials<<<dim3(Bc, NCH), Hc*Dc>>>(V);        // 7
    k4c_cumsum<<<dim3(Bc, NCH), Hc*Dc>>>(V, out);     // 8
    k5_combine_scatter<<<dim3(Uc, BHc), Dc>>>(out);   // 9
}

// round 12
// speedup vs baseline: 1.2113x; 1.1265x over previous
#include <cuda_runtime.h>
#include <math_constants.h>

#define Bc 8
#define Lc 4096
#define Hc 8
#define Dc 64
#define Sc 45
#define Uc 45
#define BHc (Bc*Hc)
#define NSPLIT 8
#define KSPLIT (Lc/NSPLIT)
#define TK 64
#define NCH 64
#define CHL (Lc/NCH)
#define KR 256
#define NKR (Lc/KR)            // 16
#define ETOT (Lc*Sc)
#define K1_SMEM (KR*Dc*4)      // 64 KB
#define FIXSCALE 16777216.0f

// ---- scratch ----
__device__ int   g_idx[ETOT];
__device__ int   g_cnt[NKR*Lc];
__device__ int   g_qofs[NKR*Lc];
__device__ unsigned int g_pack[ETOT];   // (q<<8)|kl, sorted by (krange,q,s)
__device__ unsigned int g_Mmax[BHc*Lc];
__device__ unsigned long long g_Msum[BHc*Lc];
__device__ int   g_top[BHc*Uc];
__device__ float g_pm[BHc*Uc*NSPLIT];
__device__ float g_pl[BHc*Uc*NSPLIT];
__device__ float g_pacc[BHc*Uc*NSPLIT*Dc];
__device__ float g_ps[Bc*NCH*Hc*Dc];

// ============================================================
// b_prep: dtype detect + convert + per-krange counts + zero accums
// ============================================================
__global__ void __launch_bounds__(256) b_prep(const void* __restrict__ raw)
{
    __shared__ unsigned int red[256];
    const unsigned int* p = (const unsigned int*)raw;
    unsigned int acc = 0;
    for (int j = 1 + 2*threadIdx.x; j < 1024; j += 512) acc |= p[j];
    red[threadIdx.x] = acc;
    __syncthreads();
    for (int o = 128; o > 0; o >>= 1) {
        if (threadIdx.x < o) red[threadIdx.x] |= red[threadIdx.x + o];
        __syncthreads();
    }
    int mode64 = (red[0] == 0u) ? 1 : 0;

    int nthr = gridDim.x * 256;
    int gt = blockIdx.x*256 + threadIdx.x;
    for (int i = gt; i < BHc*Lc; i += nthr) {
        g_Mmax[i] = 0u;
        g_Msum[i] = 0ull;
    }

    int q = gt;
    if (q >= Lc) return;
    int c[NKR];
    #pragma unroll
    for (int i = 0; i < NKR; i++) c[i] = 0;
    for (int s = 0; s < Sc; s++) {
        int v;
        if (mode64) v = (int)((const long long*)raw)[q*Sc + s];
        else        v = ((const int*)raw)[q*Sc + s];
        g_idx[q*Sc + s] = v;
        c[v >> 8]++;
    }
    #pragma unroll
    for (int i = 0; i < NKR; i++) g_cnt[i*Lc + q] = c[i];
}

// ============================================================
// b_scan: block per krange; exclusive scan over q + global base
// ============================================================
__global__ void __launch_bounds__(512) b_scan()
{
    __shared__ int part[512];
    __shared__ int sbase[512];
    int kr = blockIdx.x, t = threadIdx.x;
    int bacc = 0;
    for (int i = t; i < kr*Lc; i += 512) bacc += g_cnt[i];
    sbase[t] = bacc;
    __syncthreads();
    for (int o = 256; o > 0; o >>= 1) {
        if (t < o) sbase[t] += sbase[t + o];
        __syncthreads();
    }
    int base = sbase[0];

    int v[8], pre[8], sum = 0;
    for (int j = 0; j < 8; j++) {
        v[j] = g_cnt[kr*Lc + t*8 + j];
        pre[j] = sum; sum += v[j];
    }
    part[t] = sum;
    __syncthreads();
    for (int off = 1; off < 512; off <<= 1) {
        int x = (t >= off) ? part[t-off] : 0;
        __syncthreads();
        part[t] += x;
        __syncthreads();
    }
    int excl = part[t] - sum;
    for (int j = 0; j < 8; j++)
        g_qofs[kr*Lc + t*8 + j] = base + excl + pre[j];
}

// ============================================================
// b_fill: thread per q, deterministic sequential cursors.
// ============================================================
__global__ void __launch_bounds__(256) b_fill()
{
    int q = blockIdx.x * 256 + threadIdx.x;
    if (q >= Lc) return;
    int cur[NKR];
    #pragma unroll
    for (int i = 0; i < NKR; i++) cur[i] = g_qofs[i*Lc + q];
    unsigned int qb = (unsigned int)q << 8;
    for (int s = 0; s < Sc; s++) {
        int k = g_idx[q*Sc + s];
        int kr = k >> 8;
        g_pack[cur[kr]++] = qb | ((unsigned int)k & 255u);
    }
}

// ============================================================
// K1 (R9 winner): key-tiled scoring, contiguous spans, per-q-run
// register accumulation with conditional Q reload. 1024 threads,
// 2 blocks/SM.
// ============================================================
__global__ void __launch_bounds__(1024) k1_scores(
    const float* __restrict__ Q, const float* __restrict__ K)
{
    extern __shared__ float4 Ks4[];   // [KR][16] = 64KB
    int kr = blockIdx.x, bh = blockIdx.y;
    int b = bh >> 3, h = bh & 7;
    int tid = threadIdx.x;
    const float4* Q4 = (const float4*)Q;
    const float4* K4 = (const float4*)K;

    int kb = kr * KR;
    for (int i = tid; i < KR*16; i += 1024) {
        int row = i >> 4, part = i & 15;
        Ks4[i] = K4[(((b*Lc + kb + row)*Hc + h) << 4) + part];
    }
    __syncthreads();

    int start = g_qofs[kr*Lc];
    int end   = (kr == NKR-1) ? ETOT : g_qofs[(kr+1)*Lc];
    int n = end - start;
    int gid = tid >> 3, t = tid & 7;
    int per = (n + 127) >> 7;
    int e0 = gid * per;
    int e1 = min(n, e0 + per);
    const int qrow_base = ((b*Lc*Hc + h) << 4) + 2*t;
    const int mbase = bh * Lc;
    const int t2 = 2*t;
    const unsigned int* __restrict__ pk = g_pack + start;

    int qcur = -1;
    float runMax = -CUDART_INF_F, runSum = 0.f;
    float4 qa = make_float4(0.f,0.f,0.f,0.f), qb = qa;

    #pragma unroll 4
    for (int e = e0; e < e1; e++) {
        unsigned int en = pk[e];
        int q = (int)(en >> 8);
        if (q != qcur) {
            if (t == 0 && qcur >= 0) {
                unsigned int u = __float_as_uint(runMax);
                unsigned int key = (u & 0x80000000u) ? ~u : (u | 0x80000000u);
                atomicMax(&g_Mmax[mbase + qcur], key);
                atomicAdd(&g_Msum[mbase + qcur],
                          (unsigned long long)(long long)__float2ll_rn(runSum * FIXSCALE));
            }
            qcur = q;
            runMax = -CUDART_INF_F; runSum = 0.f;
            const float4* qp = &Q4[qrow_base + (q << 7)];
            qa = __ldg(qp); qb = __ldg(qp + 1);
        }
        int ki = (int)((en & 255u) << 4) + t2;
        float4 ka = Ks4[ki], kc = Ks4[ki + 1];
        float d = qa.x*ka.x + qa.y*ka.y + qa.z*ka.z + qa.w*ka.w
                + qb.x*kc.x + qb.y*kc.y + qb.z*kc.z + qb.w*kc.w;
        d += __shfl_xor_sync(0xffffffffu, d, 1, 8);
        d += __shfl_xor_sync(0xffffffffu, d, 2, 8);
        d += __shfl_xor_sync(0xffffffffu, d, 4, 8);
        runMax = fmaxf(runMax, d);
        runSum += d;
    }
    if (t == 0 && qcur >= 0) {
        unsigned int u = __float_as_uint(runMax);
        unsigned int key = (u & 0x80000000u) ? ~u : (u | 0x80000000u);
        atomicMax(&g_Mmax[mbase + qcur], key);
        atomicAdd(&g_Msum[mbase + qcur],
                  (unsigned long long)(long long)__float2ll_rn(runSum * FIXSCALE));
    }
}

// ============================================================
// K2: M from (max,sum) + radix top-45, 512 threads
// ============================================================
__global__ void __launch_bounds__(512) k2_topk()
{
    __shared__ unsigned int keys[Lc];
    __shared__ int hist[256];
    __shared__ int sel_bin, sel_rem, cnt;
    int bh = blockIdx.x, tid = threadIdx.x;
    for (int i = tid; i < Lc; i += 512) {
        unsigned int mk = g_Mmax[bh*Lc + i];
        unsigned int uu = (mk & 0x80000000u) ? (mk & 0x7FFFFFFFu) : ~mk;
        float mmax = __uint_as_float(uu);
        long long sll = (long long)g_Msum[bh*Lc + i];
        float M = mmax - (float)sll * (1.0f / (FIXSCALE * (float)Lc));
        unsigned int u = __float_as_uint(M);
        keys[i] = (u & 0x80000000u) ? ~u : (u | 0x80000000u);
    }
    if (tid == 0) cnt = 0;
    __syncthreads();
    unsigned int prefix = 0; int need = Uc;
    for (int shift = 24; shift >= 0; shift -= 8) {
        if (tid < 256) hist[tid] = 0;
        __syncthreads();
        for (int i = tid; i < Lc; i += 512) {
            unsigned int k = keys[i];
            if (shift == 24 || (k >> (shift+8)) == prefix)
                atomicAdd(&hist[(k >> shift) & 255], 1);
        }
        __syncthreads();
        for (int off = 1; off < 256; off <<= 1) {
            int v = (tid < 256 && tid + off < 256) ? hist[tid + off] : 0;
            __syncthreads();
            if (tid < 256) hist[tid] += v;
            __syncthreads();
        }
        if (tid < 256) {
            int S  = hist[tid];
            int Sn = (tid < 255) ? hist[tid + 1] : 0;
            if (S >= need && Sn < need) { sel_bin = tid; sel_rem = need - Sn; }
        }
        __syncthreads();
        prefix = (prefix << 8) | (unsigned int)sel_bin;
        need = sel_rem;
        __syncthreads();
    }
    for (int i = tid; i < Lc; i += 512) {
        if (keys[i] > prefix) { int p = atomicAdd(&cnt, 1); g_top[bh*Uc + p] = i; }
    }
    __syncthreads();
    for (int i = tid; i < Lc; i += 512) {
        if (keys[i] == prefix) {
            int p = atomicAdd(&cnt, 1);
            if (p < Uc) g_top[bh*Uc + p] = i;
        }
    }
}

// ============================================================
// K3: flash attention, joint 3-u per warp (shared LDS/shfl)
// ============================================================
__global__ void __launch_bounds__(512) k3_attn(
    const float* __restrict__ Q, const float* __restrict__ K,
    const float* __restrict__ V)
{
    __shared__ float Qs[Uc][Dc];
    __shared__ int   qpos_s[Uc];
    __shared__ float Kt[Dc][TK+1];
    __shared__ __align__(16) float Vt[TK][Dc];
    int split = blockIdx.x, bh = blockIdx.y;
    int b = bh >> 3, h = bh & 7;
    int tid = threadIdx.x, lane = tid & 31, w = tid >> 5;

    if (tid < Uc) qpos_s[tid] = g_top[bh*Uc + tid];
    __syncthreads();
    for (int i = tid; i < Uc*Dc; i += 512) {
        int u = i >> 6, d = i & 63;
        int qp = qpos_s[u];
        Qs[u][d] = Q[(((b*Lc + qp)*Hc + h) << 6) + d] * 0.125f;
    }
    __syncthreads();

    int maxqp = 0;
    for (int u = 0; u < Uc; u++) maxqp = max(maxqp, qpos_s[u]);
    int kb0 = split * KSPLIT;
    int ntiles = 0;
    if (maxqp >= kb0) {
        int nn = (maxqp - kb0) / TK + 1;
        ntiles = nn < (KSPLIT/TK) ? nn : (KSPLIT/TK);
    }

    int u0 = w*3;
    int qp[3]; bool val[3];
    #pragma unroll
    for (int j = 0; j < 3; j++) {
        int u = u0 + j;
        val[j] = (u < Uc);
        qp[j] = val[j] ? qpos_s[u] : -0x40000000;
    }
    int wqmax = max(qp[0], max(qp[1], qp[2]));

    float m[3], lsum[3], acc0[3], acc1[3];
    #pragma unroll
    for (int j = 0; j < 3; j++) { m[j] = -CUDART_INF_F; lsum[j]=0.f; acc0[j]=0.f; acc1[j]=0.f; }

    const float4* K4 = (const float4*)K;
    const float4* V4 = (const float4*)V;

    for (int tile = 0; tile < ntiles; tile++) {
        int kb = kb0 + tile * TK;
        for (int i = tid; i < TK*16; i += 512) {
            int k = i >> 4, d4 = i & 15;
            int gbase = (((b*Lc + kb + k)*Hc + h) << 4) + d4;
            float4 kv = K4[gbase];
            int d = d4 * 4;
            Kt[d][k] = kv.x; Kt[d+1][k] = kv.y; Kt[d+2][k] = kv.z; Kt[d+3][k] = kv.w;
            ((float4*)&Vt[k][0])[d4] = V4[gbase];
        }
        __syncthreads();
        if (wqmax >= kb) {
            float s0[3] = {0.f,0.f,0.f}, s1[3] = {0.f,0.f,0.f};
            #pragma unroll 8
            for (int d = 0; d < Dc; d++) {
                float kt0 = Kt[d][lane], kt1 = Kt[d][lane+32];
                #pragma unroll
                for (int j = 0; j < 3; j++) {
                    float qd = Qs[min(u0+j, Uc-1)][d];
                    s0[j] += qd * kt0;
                    s1[j] += qd * kt1;
                }
            }
            float p0[3], p1[3];
            int kmax = 0;
            #pragma unroll
            for (int j = 0; j < 3; j++) {
                if (val[j] && qp[j] >= kb) {
                    int nk = min(TK, qp[j] - kb + 1);
                    kmax = max(kmax, nk);
                    float t0 = (lane      < nk) ? s0[j] : -CUDART_INF_F;
                    float t1 = (lane + 32 < nk) ? s1[j] : -CUDART_INF_F;
                    float tm = fmaxf(t0, t1);
                    #pragma unroll
                    for (int o = 16; o > 0; o >>= 1) tm = fmaxf(tm, __shfl_xor_sync(0xffffffffu, tm, o));
                    float newm = fmaxf(m[j], tm);
                    p0[j] = __expf(t0 - newm);
                    p1[j] = __expf(t1 - newm);
                    float ps = p0[j] + p1[j];
                    #pragma unroll
                    for (int o = 16; o > 0; o >>= 1) ps += __shfl_xor_sync(0xffffffffu, ps, o);
                    float cf = __expf(m[j] - newm);
                    lsum[j] = lsum[j]*cf + ps;
                    m[j] = newm;
                    acc0[j] *= cf; acc1[j] *= cf;
                } else { p0[j] = 0.f; p1[j] = 0.f; }
            }
            int k1end = min(kmax, 32);
            for (int k = 0; k < k1end; k++) {
                float vt0 = Vt[k][lane], vt1 = Vt[k][lane+32];
                #pragma unroll
                for (int j = 0; j < 3; j++) {
                    float pk = __shfl_sync(0xffffffffu, p0[j], k);
                    acc0[j] += pk * vt0;
                    acc1[j] += pk * vt1;
                }
            }
            for (int k = 32; k < kmax; k++) {
                float vt0 = Vt[k][lane], vt1 = Vt[k][lane+32];
                #pragma unroll
                for (int j = 0; j < 3; j++) {
                    float pk = __shfl_sync(0xffffffffu, p1[j], k - 32);
                    acc0[j] += pk * vt0;
                    acc1[j] += pk * vt1;
                }
            }
        }
        __syncthreads();
    }

    #pragma unroll
    for (int j = 0; j < 3; j++) {
        if (!val[j]) continue;
        int base = ((bh*Uc + u0 + j))*NSPLIT + split;
        if (qp[j] < kb0) {
            if (lane == 0) { g_pm[base] = -CUDART_INF_F; g_pl[base] = 0.f; }
            g_pacc[base*Dc + lane] = 0.f;
            g_pacc[base*Dc + lane + 32] = 0.f;
        } else {
            if (lane == 0) { g_pm[base] = m[j]; g_pl[base] = lsum[j]; }
            g_pacc[base*Dc + lane] = acc0[j];
            g_pacc[base*Dc + lane + 32] = acc1[j];
        }
    }
}

// ============================================================
// K4a: per-chunk partial sums. K4c: self-computed prefix + cumsum.
// ============================================================
__global__ void __launch_bounds__(512) k4a_partials(const float* __restrict__ V)
{
    int b = blockIdx.x, ch = blockIdx.y, tid = threadIdx.x;
    float s = 0.f;
    int base = (b*Lc + ch*CHL) * (Hc*Dc) + tid;
    #pragma unroll 4
    for (int l = 0; l < CHL; l++) s += V[base + l*(Hc*Dc)];
    g_ps[(b*NCH + ch)*(Hc*Dc) + tid] = s;
}

__global__ void __launch_bounds__(512) k4c_cumsum(const float* __restrict__ V,
                                                  float* __restrict__ out)
{
    int b = blockIdx.x, ch = blockIdx.y, tid = threadIdx.x;
    float acc = 0.f;
    for (int i = 0; i < ch; i++)
        acc += g_ps[(b*NCH + i)*(Hc*Dc) + tid];
    int base = (b*Lc + ch*CHL) * (Hc*Dc) + tid;
    #pragma unroll 4
    for (int l = 0; l < CHL; l++) {
        acc += V[base + l*(Hc*Dc)];
        out[base + l*(Hc*Dc)] = acc;
    }
}

// K5: combine split-KV partials and scatter into output
__global__ void __launch_bounds__(64) k5_combine_scatter(float* __restrict__ out)
{
    int u = blockIdx.x, bh = blockIdx.y, d = threadIdx.x;
    int b = bh >> 3, h = bh & 7;
    int base = (bh*Uc + u)*NSPLIT;
    float pm[NSPLIT], pl[NSPLIT];
    float M = -CUDART_INF_F;
    #pragma unroll
    for (int s = 0; s < NSPLIT; s++) {
        pm[s] = g_pm[base+s]; pl[s] = g_pl[base+s];
        M = fmaxf(M, pm[s]);
    }
    float Ls = 0.f, r = 0.f;
    #pragma unroll
    for (int s = 0; s < NSPLIT; s++) {
        float e = __expf(pm[s] - M);
        Ls += pl[s] * e;
        r  += g_pacc[(base+s)*Dc + d] * e;
    }
    int qp = g_top[bh*Uc + u];
    out[(((b*Lc + qp)*Hc + h) << 6) + d] = r / Ls;
}

// ============================================================
extern "C" void kernel_launch(void* const* d_in, const int* in_sizes, int n_in,
                              void* d_out, int out_size)
{
    const float* Q = (const float*)d_in[0];
    const float* K = (const float*)d_in[1];
    const float* V = (const float*)d_in[2];
    const void*  IDXRAW = d_in[3];
    float* out = (float*)d_out;

    cudaFuncSetAttribute(k1_scores, cudaFuncAttributeMaxDynamicSharedMemorySize, K1_SMEM);

    b_prep<<<64, 256>>>(IDXRAW);                      // 1
    b_scan<<<NKR, 512>>>();                           // 2
    b_fill<<<(Lc + 255)/256, 256>>>();                // 3
    k1_scores<<<dim3(NKR, BHc), 1024, K1_SMEM>>>(Q, K);  // 4 <- profiled
    k2_topk<<<BHc, 512>>>();                          // 5
    k3_attn<<<dim3(NSPLIT, BHc), 512>>>(Q, K, V);     // 6
    k4a_partials<<<dim3(Bc, NCH), Hc*Dc>>>(V);        // 7
    k4c_cumsum<<<dim3(Bc, NCH), Hc*Dc>>>(V, out);     // 8
    k5_combine_scatter<<<dim3(Uc, BHc), Dc>>>(out);   // 9
}

// round 13
// speedup vs baseline: 1.4802x; 1.2220x over previous
#include <cuda_runtime.h>
#include <math_constants.h>

#define Bc 8
#define Lc 4096
#define Hc 8
#define Dc 64
#define Sc 45
#define Uc 45
#define BHc (Bc*Hc)
#define NSPLIT 8
#define KSPLIT (Lc/NSPLIT)
#define TK 64
#define NCH 64
#define CHL (Lc/NCH)
#define KR 256
#define NKR (Lc/KR)            // 16
#define ETOT (Lc*Sc)
#define K1_SMEM (KR*Dc*4)      // 64 KB
#define FIXSCALE 16777216.0f

// ---- scratch ----
__device__ int   g_idx[ETOT];
__device__ int   g_cnt[NKR*Lc];
__device__ int   g_qofs[NKR*Lc];
__device__ unsigned int g_pack[ETOT];   // (q<<8)|kl, sorted by (krange,q,s)
__device__ unsigned int g_Mmax[BHc*Lc];
__device__ unsigned long long g_Msum[BHc*Lc];
__device__ int   g_top[BHc*Uc];
__device__ float g_pm[BHc*Uc*NSPLIT];
__device__ float g_pl[BHc*Uc*NSPLIT];
__device__ float g_pacc[BHc*Uc*NSPLIT*Dc];
__device__ float g_ps[Bc*NCH*Hc*Dc];

// ============================================================
// b_prep: dtype detect + convert + per-krange counts + zero accums
// ============================================================
__global__ void __launch_bounds__(256) b_prep(const void* __restrict__ raw)
{
    __shared__ unsigned int red[256];
    const unsigned int* p = (const unsigned int*)raw;
    unsigned int acc = 0;
    for (int j = 1 + 2*threadIdx.x; j < 1024; j += 512) acc |= p[j];
    red[threadIdx.x] = acc;
    __syncthreads();
    for (int o = 128; o > 0; o >>= 1) {
        if (threadIdx.x < o) red[threadIdx.x] |= red[threadIdx.x + o];
        __syncthreads();
    }
    int mode64 = (red[0] == 0u) ? 1 : 0;

    int nthr = gridDim.x * 256;
    int gt = blockIdx.x*256 + threadIdx.x;
    for (int i = gt; i < BHc*Lc; i += nthr) {
        g_Mmax[i] = 0u;
        g_Msum[i] = 0ull;
    }

    int q = gt;
    if (q >= Lc) return;
    int c[NKR];
    #pragma unroll
    for (int i = 0; i < NKR; i++) c[i] = 0;
    for (int s = 0; s < Sc; s++) {
        int v;
        if (mode64) v = (int)((const long long*)raw)[q*Sc + s];
        else        v = ((const int*)raw)[q*Sc + s];
        g_idx[q*Sc + s] = v;
        c[v >> 8]++;
    }
    #pragma unroll
    for (int i = 0; i < NKR; i++) g_cnt[i*Lc + q] = c[i];
}

// ============================================================
// b_scan: block per krange; exclusive scan over q + global base
// ============================================================
__global__ void __launch_bounds__(512) b_scan()
{
    __shared__ int part[512];
    __shared__ int sbase[512];
    int kr = blockIdx.x, t = threadIdx.x;
    int bacc = 0;
    for (int i = t; i < kr*Lc; i += 512) bacc += g_cnt[i];
    sbase[t] = bacc;
    __syncthreads();
    for (int o = 256; o > 0; o >>= 1) {
        if (t < o) sbase[t] += sbase[t + o];
        __syncthreads();
    }
    int base = sbase[0];

    int v[8], pre[8], sum = 0;
    for (int j = 0; j < 8; j++) {
        v[j] = g_cnt[kr*Lc + t*8 + j];
        pre[j] = sum; sum += v[j];
    }
    part[t] = sum;
    __syncthreads();
    for (int off = 1; off < 512; off <<= 1) {
        int x = (t >= off) ? part[t-off] : 0;
        __syncthreads();
        part[t] += x;
        __syncthreads();
    }
    int excl = part[t] - sum;
    for (int j = 0; j < 8; j++)
        g_qofs[kr*Lc + t*8 + j] = base + excl + pre[j];
}

// ============================================================
// b_fill: thread per q, deterministic sequential cursors.
// ============================================================
__global__ void __launch_bounds__(256) b_fill()
{
    int q = blockIdx.x * 256 + threadIdx.x;
    if (q >= Lc) return;
    int cur[NKR];
    #pragma unroll
    for (int i = 0; i < NKR; i++) cur[i] = g_qofs[i*Lc + q];
    unsigned int qb = (unsigned int)q << 8;
    for (int s = 0; s < Sc; s++) {
        int k = g_idx[q*Sc + s];
        int kr = k >> 8;
        g_pack[cur[kr]++] = qb | ((unsigned int)k & 255u);
    }
}

// ============================================================
// K1: key-tiled scoring. Lane t reads K/Q parts {t, t+8} ->
// conflict-free LDS.128 phases (banks covered exactly once).
// Per-q-run register accumulation + run atomics. 2 blocks/SM.
// ============================================================
__global__ void __launch_bounds__(1024) k1_scores(
    const float* __restrict__ Q, const float* __restrict__ K)
{
    extern __shared__ float4 Ks4[];   // [KR][16] = 64KB
    int kr = blockIdx.x, bh = blockIdx.y;
    int b = bh >> 3, h = bh & 7;
    int tid = threadIdx.x;
    const float4* Q4 = (const float4*)Q;
    const float4* K4 = (const float4*)K;

    int kb = kr * KR;
    for (int i = tid; i < KR*16; i += 1024) {
        int row = i >> 4, part = i & 15;
        Ks4[i] = K4[(((b*Lc + kb + row)*Hc + h) << 4) + part];
    }
    __syncthreads();

    int start = g_qofs[kr*Lc];
    int end   = (kr == NKR-1) ? ETOT : g_qofs[(kr+1)*Lc];
    int n = end - start;
    int gid = tid >> 3, t = tid & 7;
    int per = (n + 127) >> 7;
    int e0 = gid * per;
    int e1 = min(n, e0 + per);
    const int qrow_base = ((b*Lc*Hc + h) << 4) + t;   // parts t and t+8
    const int mbase = bh * Lc;
    const unsigned int* __restrict__ pk = g_pack + start;

    int qcur = -1;
    float runMax = -CUDART_INF_F, runSum = 0.f;
    float4 qa = make_float4(0.f,0.f,0.f,0.f), qb = qa;

    #pragma unroll 4
    for (int e = e0; e < e1; e++) {
        unsigned int en = pk[e];
        int q = (int)(en >> 8);
        if (q != qcur) {
            if (t == 0 && qcur >= 0) {
                unsigned int u = __float_as_uint(runMax);
                unsigned int key = (u & 0x80000000u) ? ~u : (u | 0x80000000u);
                atomicMax(&g_Mmax[mbase + qcur], key);
                atomicAdd(&g_Msum[mbase + qcur],
                          (unsigned long long)(long long)__float2ll_rn(runSum * FIXSCALE));
            }
            qcur = q;
            runMax = -CUDART_INF_F; runSum = 0.f;
            const float4* qp = &Q4[qrow_base + (q << 7)];
            qa = __ldg(qp); qb = __ldg(qp + 8);
        }
        int ki = (int)((en & 255u) << 4) + t;
        float4 ka = Ks4[ki], kc = Ks4[ki + 8];
        float d = qa.x*ka.x + qa.y*ka.y + qa.z*ka.z + qa.w*ka.w
                + qb.x*kc.x + qb.y*kc.y + qb.z*kc.z + qb.w*kc.w;
        d += __shfl_xor_sync(0xffffffffu, d, 1, 8);
        d += __shfl_xor_sync(0xffffffffu, d, 2, 8);
        d += __shfl_xor_sync(0xffffffffu, d, 4, 8);
        runMax = fmaxf(runMax, d);
        runSum += d;
    }
    if (t == 0 && qcur >= 0) {
        unsigned int u = __float_as_uint(runMax);
        unsigned int key = (u & 0x80000000u) ? ~u : (u | 0x80000000u);
        atomicMax(&g_Mmax[mbase + qcur], key);
        atomicAdd(&g_Msum[mbase + qcur],
                  (unsigned long long)(long long)__float2ll_rn(runSum * FIXSCALE));
    }
}

// ============================================================
// K2: M from (max,sum) + radix top-45, 512 threads
// ============================================================
__global__ void __launch_bounds__(512) k2_topk()
{
    __shared__ unsigned int keys[Lc];
    __shared__ int hist[256];
    __shared__ int sel_bin, sel_rem, cnt;
    int bh = blockIdx.x, tid = threadIdx.x;
    for (int i = tid; i < Lc; i += 512) {
        unsigned int mk = g_Mmax[bh*Lc + i];
        unsigned int uu = (mk & 0x80000000u) ? (mk & 0x7FFFFFFFu) : ~mk;
        float mmax = __uint_as_float(uu);
        long long sll = (long long)g_Msum[bh*Lc + i];
        float M = mmax - (float)sll * (1.0f / (FIXSCALE * (float)Lc));
        unsigned int u = __float_as_uint(M);
        keys[i] = (u & 0x80000000u) ? ~u : (u | 0x80000000u);
    }
    if (tid == 0) cnt = 0;
    __syncthreads();
    unsigned int prefix = 0; int need = Uc;
    for (int shift = 24; shift >= 0; shift -= 8) {
        if (tid < 256) hist[tid] = 0;
        __syncthreads();
        for (int i = tid; i < Lc; i += 512) {
            unsigned int k = keys[i];
            if (shift == 24 || (k >> (shift+8)) == prefix)
                atomicAdd(&hist[(k >> shift) & 255], 1);
        }
        __syncthreads();
        for (int off = 1; off < 256; off <<= 1) {
            int v = (tid < 256 && tid + off < 256) ? hist[tid + off] : 0;
            __syncthreads();
            if (tid < 256) hist[tid] += v;
            __syncthreads();
        }
        if (tid < 256) {
            int S  = hist[tid];
            int Sn = (tid < 255) ? hist[tid + 1] : 0;
            if (S >= need && Sn < need) { sel_bin = tid; sel_rem = need - Sn; }
        }
        __syncthreads();
        prefix = (prefix << 8) | (unsigned int)sel_bin;
        need = sel_rem;
        __syncthreads();
    }
    for (int i = tid; i < Lc; i += 512) {
        if (keys[i] > prefix) { int p = atomicAdd(&cnt, 1); g_top[bh*Uc + p] = i; }
    }
    __syncthreads();
    for (int i = tid; i < Lc; i += 512) {
        if (keys[i] == prefix) {
            int p = atomicAdd(&cnt, 1);
            if (p < Uc) g_top[bh*Uc + p] = i;
        }
    }
}

// ============================================================
// K3: flash attention, joint 3-u per warp (shared LDS/shfl)
// ============================================================
__global__ void __launch_bounds__(512) k3_attn(
    const float* __restrict__ Q, const float* __restrict__ K,
    const float* __restrict__ V)
{
    __shared__ float Qs[Uc][Dc];
    __shared__ int   qpos_s[Uc];
    __shared__ float Kt[Dc][TK+1];
    __shared__ __align__(16) float Vt[TK][Dc];
    int split = blockIdx.x, bh = blockIdx.y;
    int b = bh >> 3, h = bh & 7;
    int tid = threadIdx.x, lane = tid & 31, w = tid >> 5;

    if (tid < Uc) qpos_s[tid] = g_top[bh*Uc + tid];
    __syncthreads();
    for (int i = tid; i < Uc*Dc; i += 512) {
        int u = i >> 6, d = i & 63;
        int qp = qpos_s[u];
        Qs[u][d] = Q[(((b*Lc + qp)*Hc + h) << 6) + d] * 0.125f;
    }
    __syncthreads();

    int maxqp = 0;
    for (int u = 0; u < Uc; u++) maxqp = max(maxqp, qpos_s[u]);
    int kb0 = split * KSPLIT;
    int ntiles = 0;
    if (maxqp >= kb0) {
        int nn = (maxqp - kb0) / TK + 1;
        ntiles = nn < (KSPLIT/TK) ? nn : (KSPLIT/TK);
    }

    int u0 = w*3;
    int qp[3]; bool val[3];
    #pragma unroll
    for (int j = 0; j < 3; j++) {
        int u = u0 + j;
        val[j] = (u < Uc);
        qp[j] = val[j] ? qpos_s[u] : -0x40000000;
    }
    int wqmax = max(qp[0], max(qp[1], qp[2]));

    float m[3], lsum[3], acc0[3], acc1[3];
    #pragma unroll
    for (int j = 0; j < 3; j++) { m[j] = -CUDART_INF_F; lsum[j]=0.f; acc0[j]=0.f; acc1[j]=0.f; }

    const float4* K4 = (const float4*)K;
    const float4* V4 = (const float4*)V;

    for (int tile = 0; tile < ntiles; tile++) {
        int kb = kb0 + tile * TK;
        for (int i = tid; i < TK*16; i += 512) {
            int k = i >> 4, d4 = i & 15;
            int gbase = (((b*Lc + kb + k)*Hc + h) << 4) + d4;
            float4 kv = K4[gbase];
            int d = d4 * 4;
            Kt[d][k] = kv.x; Kt[d+1][k] = kv.y; Kt[d+2][k] = kv.z; Kt[d+3][k] = kv.w;
            ((float4*)&Vt[k][0])[d4] = V4[gbase];
        }
        __syncthreads();
        if (wqmax >= kb) {
            float s0[3] = {0.f,0.f,0.f}, s1[3] = {0.f,0.f,0.f};
            #pragma unroll 8
            for (int d = 0; d < Dc; d++) {
                float kt0 = Kt[d][lane], kt1 = Kt[d][lane+32];
                #pragma unroll
                for (int j = 0; j < 3; j++) {
                    float qd = Qs[min(u0+j, Uc-1)][d];
                    s0[j] += qd * kt0;
                    s1[j] += qd * kt1;
                }
            }
            float p0[3], p1[3];
            int kmax = 0;
            #pragma unroll
            for (int j = 0; j < 3; j++) {
                if (val[j] && qp[j] >= kb) {
                    int nk = min(TK, qp[j] - kb + 1);
                    kmax = max(kmax, nk);
                    float t0 = (lane      < nk) ? s0[j] : -CUDART_INF_F;
                    float t1 = (lane + 32 < nk) ? s1[j] : -CUDART_INF_F;
                    float tm = fmaxf(t0, t1);
                    #pragma unroll
                    for (int o = 16; o > 0; o >>= 1) tm = fmaxf(tm, __shfl_xor_sync(0xffffffffu, tm, o));
                    float newm = fmaxf(m[j], tm);
                    p0[j] = __expf(t0 - newm);
                    p1[j] = __expf(t1 - newm);
                    float ps = p0[j] + p1[j];
                    #pragma unroll
                    for (int o = 16; o > 0; o >>= 1) ps += __shfl_xor_sync(0xffffffffu, ps, o);
                    float cf = __expf(m[j] - newm);
                    lsum[j] = lsum[j]*cf + ps;
                    m[j] = newm;
                    acc0[j] *= cf; acc1[j] *= cf;
                } else { p0[j] = 0.f; p1[j] = 0.f; }
            }
            int k1end = min(kmax, 32);
            for (int k = 0; k < k1end; k++) {
                float vt0 = Vt[k][lane], vt1 = Vt[k][lane+32];
                #pragma unroll
                for (int j = 0; j < 3; j++) {
                    float pk = __shfl_sync(0xffffffffu, p0[j], k);
                    acc0[j] += pk * vt0;
                    acc1[j] += pk * vt1;
                }
            }
            for (int k = 32; k < kmax; k++) {
                float vt0 = Vt[k][lane], vt1 = Vt[k][lane+32];
                #pragma unroll
                for (int j = 0; j < 3; j++) {
                    float pk = __shfl_sync(0xffffffffu, p1[j], k - 32);
                    acc0[j] += pk * vt0;
                    acc1[j] += pk * vt1;
                }
            }
        }
        __syncthreads();
    }

    #pragma unroll
    for (int j = 0; j < 3; j++) {
        if (!val[j]) continue;
        int base = ((bh*Uc + u0 + j))*NSPLIT + split;
        if (qp[j] < kb0) {
            if (lane == 0) { g_pm[base] = -CUDART_INF_F; g_pl[base] = 0.f; }
            g_pacc[base*Dc + lane] = 0.f;
            g_pacc[base*Dc + lane + 32] = 0.f;
        } else {
            if (lane == 0) { g_pm[base] = m[j]; g_pl[base] = lsum[j]; }
            g_pacc[base*Dc + lane] = acc0[j];
            g_pacc[base*Dc + lane + 32] = acc1[j];
        }
    }
}

// ============================================================
// K4a: per-chunk partial sums. K4c: self-computed prefix + cumsum.
// ============================================================
__global__ void __launch_bounds__(512) k4a_partials(const float* __restrict__ V)
{
    int b = blockIdx.x, ch = blockIdx.y, tid = threadIdx.x;
    float s = 0.f;
    int base = (b*Lc + ch*CHL) * (Hc*Dc) + tid;
    #pragma unroll 4
    for (int l = 0; l < CHL; l++) s += V[base + l*(Hc*Dc)];
    g_ps[(b*NCH + ch)*(Hc*Dc) + tid] = s;
}

__global__ void __launch_bounds__(512) k4c_cumsum(const float* __restrict__ V,
                                                  float* __restrict__ out)
{
    int b = blockIdx.x, ch = blockIdx.y, tid = threadIdx.x;
    float acc = 0.f;
    for (int i = 0; i < ch; i++)
        acc += g_ps[(b*NCH + i)*(Hc*Dc) + tid];
    int base = (b*Lc + ch*CHL) * (Hc*Dc) + tid;
    #pragma unroll 4
    for (int l = 0; l < CHL; l++) {
        acc += V[base + l*(Hc*Dc)];
        out[base + l*(Hc*Dc)] = acc;
    }
}

// K5: combine split-KV partials and scatter into output
__global__ void __launch_bounds__(64) k5_combine_scatter(float* __restrict__ out)
{
    int u = blockIdx.x, bh = blockIdx.y, d = threadIdx.x;
    int b = bh >> 3, h = bh & 7;
    int base = (bh*Uc + u)*NSPLIT;
    float pm[NSPLIT], pl[NSPLIT];
    float M = -CUDART_INF_F;
    #pragma unroll
    for (int s = 0; s < NSPLIT; s++) {
        pm[s] = g_pm[base+s]; pl[s] = g_pl[base+s];
        M = fmaxf(M, pm[s]);
    }
    float Ls = 0.f, r = 0.f;
    #pragma unroll
    for (int s = 0; s < NSPLIT; s++) {
        float e = __expf(pm[s] - M);
        Ls += pl[s] * e;
        r  += g_pacc[(base+s)*Dc + d] * e;
    }
    int qp = g_top[bh*Uc + u];
    out[(((b*Lc + qp)*Hc + h) << 6) + d] = r / Ls;
}

// ============================================================
extern "C" void kernel_launch(void* const* d_in, const int* in_sizes, int n_in,
                              void* d_out, int out_size)
{
    const float* Q = (const float*)d_in[0];
    const float* K = (const float*)d_in[1];
    const float* V = (const float*)d_in[2];
    const void*  IDXRAW = d_in[3];
    float* out = (float*)d_out;

    cudaFuncSetAttribute(k1_scores, cudaFuncAttributeMaxDynamicSharedMemorySize, K1_SMEM);

    b_prep<<<64, 256>>>(IDXRAW);                      // 1
    b_scan<<<NKR, 512>>>();                           // 2
    b_fill<<<(Lc + 255)/256, 256>>>();                // 3
    k1_scores<<<dim3(NKR, BHc), 1024, K1_SMEM>>>(Q, K);  // 4 <- profiled
    k2_topk<<<BHc, 512>>>();                          // 5
    k3_attn<<<dim3(NSPLIT, BHc), 512>>>(Q, K, V);     // 6
    k4a_partials<<<dim3(Bc, NCH), Hc*Dc>>>(V);        // 7
    k4c_cumsum<<<dim3(Bc, NCH), Hc*Dc>>>(V, out);     // 8
    k5_combine_scatter<<<dim3(Uc, BHc), Dc>>>(out);   // 9
}

// round 14
// speedup vs baseline: 1.5941x; 1.0769x over previous
#include <cuda_runtime.h>
#include <math_constants.h>

#define Bc 8
#define Lc 4096
#define Hc 8
#define Dc 64
#define Sc 45
#define Uc 45
#define BHc (Bc*Hc)
#define NSPLIT 16
#define KSPLIT (Lc/NSPLIT)
#define TK 64
#define NCH 64
#define CHL (Lc/NCH)
#define KR 256
#define NKR (Lc/KR)            // 16
#define ETOT (Lc*Sc)
#define K1_SMEM (KR*Dc*4)      // 64 KB
#define FIXSCALE 16777216.0f

// ---- scratch ----
__device__ int   g_idx[ETOT];
__device__ int   g_cnt[NKR*Lc];
__device__ int   g_qofs[NKR*Lc];
__device__ unsigned int g_pack[ETOT];   // (q<<8)|kl, sorted by (krange,q,s)
__device__ unsigned int g_Mmax[BHc*Lc];
__device__ unsigned long long g_Msum[BHc*Lc];
__device__ int   g_top[BHc*Uc];
__device__ float g_pm[BHc*Uc*NSPLIT];
__device__ float g_pl[BHc*Uc*NSPLIT];
__device__ float g_pacc[BHc*Uc*NSPLIT*Dc];
__device__ float g_ps[Bc*NCH*Hc*Dc];

// ============================================================
// b_prep: dtype detect + convert + per-krange counts + zero accums
// ============================================================
__global__ void __launch_bounds__(256) b_prep(const void* __restrict__ raw)
{
    __shared__ unsigned int red[256];
    const unsigned int* p = (const unsigned int*)raw;
    unsigned int acc = 0;
    for (int j = 1 + 2*threadIdx.x; j < 1024; j += 512) acc |= p[j];
    red[threadIdx.x] = acc;
    __syncthreads();
    for (int o = 128; o > 0; o >>= 1) {
        if (threadIdx.x < o) red[threadIdx.x] |= red[threadIdx.x + o];
        __syncthreads();
    }
    int mode64 = (red[0] == 0u) ? 1 : 0;

    int nthr = gridDim.x * 256;
    int gt = blockIdx.x*256 + threadIdx.x;
    for (int i = gt; i < BHc*Lc; i += nthr) {
        g_Mmax[i] = 0u;
        g_Msum[i] = 0ull;
    }

    int q = gt;
    if (q >= Lc) return;
    int c[NKR];
    #pragma unroll
    for (int i = 0; i < NKR; i++) c[i] = 0;
    for (int s = 0; s < Sc; s++) {
        int v;
        if (mode64) v = (int)((const long long*)raw)[q*Sc + s];
        else        v = ((const int*)raw)[q*Sc + s];
        g_idx[q*Sc + s] = v;
        c[v >> 8]++;
    }
    #pragma unroll
    for (int i = 0; i < NKR; i++) g_cnt[i*Lc + q] = c[i];
}

// ============================================================
// b_scan: block per krange; exclusive scan over q + global base
// ============================================================
__global__ void __launch_bounds__(512) b_scan()
{
    __shared__ int part[512];
    __shared__ int sbase[512];
    int kr = blockIdx.x, t = threadIdx.x;
    int bacc = 0;
    for (int i = t; i < kr*Lc; i += 512) bacc += g_cnt[i];
    sbase[t] = bacc;
    __syncthreads();
    for (int o = 256; o > 0; o >>= 1) {
        if (t < o) sbase[t] += sbase[t + o];
        __syncthreads();
    }
    int base = sbase[0];

    int v[8], pre[8], sum = 0;
    for (int j = 0; j < 8; j++) {
        v[j] = g_cnt[kr*Lc + t*8 + j];
        pre[j] = sum; sum += v[j];
    }
    part[t] = sum;
    __syncthreads();
    for (int off = 1; off < 512; off <<= 1) {
        int x = (t >= off) ? part[t-off] : 0;
        __syncthreads();
        part[t] += x;
        __syncthreads();
    }
    int excl = part[t] - sum;
    for (int j = 0; j < 8; j++)
        g_qofs[kr*Lc + t*8 + j] = base + excl + pre[j];
}

// ============================================================
// b_fill: thread per q, deterministic sequential cursors.
// ============================================================
__global__ void __launch_bounds__(256) b_fill()
{
    int q = blockIdx.x * 256 + threadIdx.x;
    if (q >= Lc) return;
    int cur[NKR];
    #pragma unroll
    for (int i = 0; i < NKR; i++) cur[i] = g_qofs[i*Lc + q];
    unsigned int qb = (unsigned int)q << 8;
    for (int s = 0; s < Sc; s++) {
        int k = g_idx[q*Sc + s];
        int kr = k >> 8;
        g_pack[cur[kr]++] = qb | ((unsigned int)k & 255u);
    }
}

// ============================================================
// K1 (banked): key-tiled scoring, conflict-free {t, t+8} parts,
// per-q-run register accumulation + run atomics. 2 blocks/SM.
// ============================================================
__global__ void __launch_bounds__(1024) k1_scores(
    const float* __restrict__ Q, const float* __restrict__ K)
{
    extern __shared__ float4 Ks4[];   // [KR][16] = 64KB
    int kr = blockIdx.x, bh = blockIdx.y;
    int b = bh >> 3, h = bh & 7;
    int tid = threadIdx.x;
    const float4* Q4 = (const float4*)Q;
    const float4* K4 = (const float4*)K;

    int kb = kr * KR;
    for (int i = tid; i < KR*16; i += 1024) {
        int row = i >> 4, part = i & 15;
        Ks4[i] = K4[(((b*Lc + kb + row)*Hc + h) << 4) + part];
    }
    __syncthreads();

    int start = g_qofs[kr*Lc];
    int end   = (kr == NKR-1) ? ETOT : g_qofs[(kr+1)*Lc];
    int n = end - start;
    int gid = tid >> 3, t = tid & 7;
    int per = (n + 127) >> 7;
    int e0 = gid * per;
    int e1 = min(n, e0 + per);
    const int qrow_base = ((b*Lc*Hc + h) << 4) + t;   // parts t and t+8
    const int mbase = bh * Lc;
    const unsigned int* __restrict__ pk = g_pack + start;

    int qcur = -1;
    float runMax = -CUDART_INF_F, runSum = 0.f;
    float4 qa = make_float4(0.f,0.f,0.f,0.f), qb = qa;

    #pragma unroll 4
    for (int e = e0; e < e1; e++) {
        unsigned int en = pk[e];
        int q = (int)(en >> 8);
        if (q != qcur) {
            if (t == 0 && qcur >= 0) {
                unsigned int u = __float_as_uint(runMax);
                unsigned int key = (u & 0x80000000u) ? ~u : (u | 0x80000000u);
                atomicMax(&g_Mmax[mbase + qcur], key);
                atomicAdd(&g_Msum[mbase + qcur],
                          (unsigned long long)(long long)__float2ll_rn(runSum * FIXSCALE));
            }
            qcur = q;
            runMax = -CUDART_INF_F; runSum = 0.f;
            const float4* qp = &Q4[qrow_base + (q << 7)];
            qa = __ldg(qp); qb = __ldg(qp + 8);
        }
        int ki = (int)((en & 255u) << 4) + t;
        float4 ka = Ks4[ki], kc = Ks4[ki + 8];
        float d = qa.x*ka.x + qa.y*ka.y + qa.z*ka.z + qa.w*ka.w
                + qb.x*kc.x + qb.y*kc.y + qb.z*kc.z + qb.w*kc.w;
        d += __shfl_xor_sync(0xffffffffu, d, 1, 8);
        d += __shfl_xor_sync(0xffffffffu, d, 2, 8);
        d += __shfl_xor_sync(0xffffffffu, d, 4, 8);
        runMax = fmaxf(runMax, d);
        runSum += d;
    }
    if (t == 0 && qcur >= 0) {
        unsigned int u = __float_as_uint(runMax);
        unsigned int key = (u & 0x80000000u) ? ~u : (u | 0x80000000u);
        atomicMax(&g_Mmax[mbase + qcur], key);
        atomicAdd(&g_Msum[mbase + qcur],
                  (unsigned long long)(long long)__float2ll_rn(runSum * FIXSCALE));
    }
}

// ============================================================
// K2: M from (max,sum) + radix top-45, 512 threads
// ============================================================
__global__ void __launch_bounds__(512) k2_topk()
{
    __shared__ unsigned int keys[Lc];
    __shared__ int hist[256];
    __shared__ int sel_bin, sel_rem, cnt;
    int bh = blockIdx.x, tid = threadIdx.x;
    for (int i = tid; i < Lc; i += 512) {
        unsigned int mk = g_Mmax[bh*Lc + i];
        unsigned int uu = (mk & 0x80000000u) ? (mk & 0x7FFFFFFFu) : ~mk;
        float mmax = __uint_as_float(uu);
        long long sll = (long long)g_Msum[bh*Lc + i];
        float M = mmax - (float)sll * (1.0f / (FIXSCALE * (float)Lc));
        unsigned int u = __float_as_uint(M);
        keys[i] = (u & 0x80000000u) ? ~u : (u | 0x80000000u);
    }
    if (tid == 0) cnt = 0;
    __syncthreads();
    unsigned int prefix = 0; int need = Uc;
    for (int shift = 24; shift >= 0; shift -= 8) {
        if (tid < 256) hist[tid] = 0;
        __syncthreads();
        for (int i = tid; i < Lc; i += 512) {
            unsigned int k = keys[i];
            if (shift == 24 || (k >> (shift+8)) == prefix)
                atomicAdd(&hist[(k >> shift) & 255], 1);
        }
        __syncthreads();
        for (int off = 1; off < 256; off <<= 1) {
            int v = (tid < 256 && tid + off < 256) ? hist[tid + off] : 0;
            __syncthreads();
            if (tid < 256) hist[tid] += v;
            __syncthreads();
        }
        if (tid < 256) {
            int S  = hist[tid];
            int Sn = (tid < 255) ? hist[tid + 1] : 0;
            if (S >= need && Sn < need) { sel_bin = tid; sel_rem = need - Sn; }
        }
        __syncthreads();
        prefix = (prefix << 8) | (unsigned int)sel_bin;
        need = sel_rem;
        __syncthreads();
    }
    for (int i = tid; i < Lc; i += 512) {
        if (keys[i] > prefix) { int p = atomicAdd(&cnt, 1); g_top[bh*Uc + p] = i; }
    }
    __syncthreads();
    for (int i = tid; i < Lc; i += 512) {
        if (keys[i] == prefix) {
            int p = atomicAdd(&cnt, 1);
            if (p < Uc) g_top[bh*Uc + p] = i;
        }
    }
}

// ============================================================
// K3: flash attention, joint 3-u per warp (shared LDS/shfl)
// ============================================================
__global__ void __launch_bounds__(512) k3_attn(
    const float* __restrict__ Q, const float* __restrict__ K,
    const float* __restrict__ V)
{
    __shared__ float Qs[Uc][Dc];
    __shared__ int   qpos_s[Uc];
    __shared__ float Kt[Dc][TK+1];
    __shared__ __align__(16) float Vt[TK][Dc];
    int split = blockIdx.x, bh = blockIdx.y;
    int b = bh >> 3, h = bh & 7;
    int tid = threadIdx.x, lane = tid & 31, w = tid >> 5;

    if (tid < Uc) qpos_s[tid] = g_top[bh*Uc + tid];
    __syncthreads();
    for (int i = tid; i < Uc*Dc; i += 512) {
        int u = i >> 6, d = i & 63;
        int qp = qpos_s[u];
        Qs[u][d] = Q[(((b*Lc + qp)*Hc + h) << 6) + d] * 0.125f;
    }
    __syncthreads();

    int maxqp = 0;
    for (int u = 0; u < Uc; u++) maxqp = max(maxqp, qpos_s[u]);
    int kb0 = split * KSPLIT;
    int ntiles = 0;
    if (maxqp >= kb0) {
        int nn = (maxqp - kb0) / TK + 1;
        ntiles = nn < (KSPLIT/TK) ? nn : (KSPLIT/TK);
    }

    int u0 = w*3;
    int qp[3]; bool val[3];
    #pragma unroll
    for (int j = 0; j < 3; j++) {
        int u = u0 + j;
        val[j] = (u < Uc);
        qp[j] = val[j] ? qpos_s[u] : -0x40000000;
    }
    int wqmax = max(qp[0], max(qp[1], qp[2]));

    float m[3], lsum[3], acc0[3], acc1[3];
    #pragma unroll
    for (int j = 0; j < 3; j++) { m[j] = -CUDART_INF_F; lsum[j]=0.f; acc0[j]=0.f; acc1[j]=0.f; }

    const float4* K4 = (const float4*)K;
    const float4* V4 = (const float4*)V;

    for (int tile = 0; tile < ntiles; tile++) {
        int kb = kb0 + tile * TK;
        for (int i = tid; i < TK*16; i += 512) {
            int k = i >> 4, d4 = i & 15;
            int gbase = (((b*Lc + kb + k)*Hc + h) << 4) + d4;
            float4 kv = K4[gbase];
            int d = d4 * 4;
            Kt[d][k] = kv.x; Kt[d+1][k] = kv.y; Kt[d+2][k] = kv.z; Kt[d+3][k] = kv.w;
            ((float4*)&Vt[k][0])[d4] = V4[gbase];
        }
        __syncthreads();
        if (wqmax >= kb) {
            float s0[3] = {0.f,0.f,0.f}, s1[3] = {0.f,0.f,0.f};
            #pragma unroll 8
            for (int d = 0; d < Dc; d++) {
                float kt0 = Kt[d][lane], kt1 = Kt[d][lane+32];
                #pragma unroll
                for (int j = 0; j < 3; j++) {
                    float qd = Qs[min(u0+j, Uc-1)][d];
                    s0[j] += qd * kt0;
                    s1[j] += qd * kt1;
                }
            }
            float p0[3], p1[3];
            int kmax = 0;
            #pragma unroll
            for (int j = 0; j < 3; j++) {
                if (val[j] && qp[j] >= kb) {
                    int nk = min(TK, qp[j] - kb + 1);
                    kmax = max(kmax, nk);
                    float t0 = (lane      < nk) ? s0[j] : -CUDART_INF_F;
                    float t1 = (lane + 32 < nk) ? s1[j] : -CUDART_INF_F;
                    float tm = fmaxf(t0, t1);
                    #pragma unroll
                    for (int o = 16; o > 0; o >>= 1) tm = fmaxf(tm, __shfl_xor_sync(0xffffffffu, tm, o));
                    float newm = fmaxf(m[j], tm);
                    p0[j] = __expf(t0 - newm);
                    p1[j] = __expf(t1 - newm);
                    float ps = p0[j] + p1[j];
                    #pragma unroll
                    for (int o = 16; o > 0; o >>= 1) ps += __shfl_xor_sync(0xffffffffu, ps, o);
                    float cf = __expf(m[j] - newm);
                    lsum[j] = lsum[j]*cf + ps;
                    m[j] = newm;
                    acc0[j] *= cf; acc1[j] *= cf;
                } else { p0[j] = 0.f; p1[j] = 0.f; }
            }
            int k1end = min(kmax, 32);
            for (int k = 0; k < k1end; k++) {
                float vt0 = Vt[k][lane], vt1 = Vt[k][lane+32];
                #pragma unroll
                for (int j = 0; j < 3; j++) {
                    float pk = __shfl_sync(0xffffffffu, p0[j], k);
                    acc0[j] += pk * vt0;
                    acc1[j] += pk * vt1;
                }
            }
            for (int k = 32; k < kmax; k++) {
                float vt0 = Vt[k][lane], vt1 = Vt[k][lane+32];
                #pragma unroll
                for (int j = 0; j < 3; j++) {
                    float pk = __shfl_sync(0xffffffffu, p1[j], k - 32);
                    acc0[j] += pk * vt0;
                    acc1[j] += pk * vt1;
                }
            }
        }
        __syncthreads();
    }

    #pragma unroll
    for (int j = 0; j < 3; j++) {
        if (!val[j]) continue;
        int base = ((bh*Uc + u0 + j))*NSPLIT + split;
        if (qp[j] < kb0) {
            if (lane == 0) { g_pm[base] = -CUDART_INF_F; g_pl[base] = 0.f; }
            g_pacc[base*Dc + lane] = 0.f;
            g_pacc[base*Dc + lane + 32] = 0.f;
        } else {
            if (lane == 0) { g_pm[base] = m[j]; g_pl[base] = lsum[j]; }
            g_pacc[base*Dc + lane] = acc0[j];
            g_pacc[base*Dc + lane + 32] = acc1[j];
        }
    }
}

// ============================================================
// K4a: per-chunk partial sums. K4c: self-computed prefix + cumsum.
// ============================================================
__global__ void __launch_bounds__(512) k4a_partials(const float* __restrict__ V)
{
    int b = blockIdx.x, ch = blockIdx.y, tid = threadIdx.x;
    float s = 0.f;
    int base = (b*Lc + ch*CHL) * (Hc*Dc) + tid;
    #pragma unroll 4
    for (int l = 0; l < CHL; l++) s += V[base + l*(Hc*Dc)];
    g_ps[(b*NCH + ch)*(Hc*Dc) + tid] = s;
}

__global__ void __launch_bounds__(512) k4c_cumsum(const float* __restrict__ V,
                                                  float* __restrict__ out)
{
    int b = blockIdx.x, ch = blockIdx.y, tid = threadIdx.x;
    float acc = 0.f;
    for (int i = 0; i < ch; i++)
        acc += g_ps[(b*NCH + i)*(Hc*Dc) + tid];
    int base = (b*Lc + ch*CHL) * (Hc*Dc) + tid;
    #pragma unroll 4
    for (int l = 0; l < CHL; l++) {
        acc += V[base + l*(Hc*Dc)];
        out[base + l*(Hc*Dc)] = acc;
    }
}

// K5: combine split-KV partials and scatter into output
__global__ void __launch_bounds__(64) k5_combine_scatter(float* __restrict__ out)
{
    int u = blockIdx.x, bh = blockIdx.y, d = threadIdx.x;
    int b = bh >> 3, h = bh & 7;
    int base = (bh*Uc + u)*NSPLIT;
    float pm[NSPLIT], pl[NSPLIT];
    float M = -CUDART_INF_F;
    #pragma unroll
    for (int s = 0; s < NSPLIT; s++) {
        pm[s] = g_pm[base+s]; pl[s] = g_pl[base+s];
        M = fmaxf(M, pm[s]);
    }
    float Ls = 0.f, r = 0.f;
    #pragma unroll
    for (int s = 0; s < NSPLIT; s++) {
        float e = __expf(pm[s] - M);
        Ls += pl[s] * e;
        r  += g_pacc[(base+s)*Dc + d] * e;
    }
    int qp = g_top[bh*Uc + u];
    out[(((b*Lc + qp)*Hc + h) << 6) + d] = r / Ls;
}

// ============================================================
extern "C" void kernel_launch(void* const* d_in, const int* in_sizes, int n_in,
                              void* d_out, int out_size)
{
    const float* Q = (const float*)d_in[0];
    const float* K = (const float*)d_in[1];
    const float* V = (const float*)d_in[2];
    const void*  IDXRAW = d_in[3];
    float* out = (float*)d_out;

    cudaFuncSetAttribute(k1_scores, cudaFuncAttributeMaxDynamicSharedMemorySize, K1_SMEM);

    // fork a side stream for the V-cumsum chain (independent of k1..k3)
    cudaStream_t s2;
    cudaStreamCreateWithFlags(&s2, cudaStreamNonBlocking);
    cudaEvent_t evFork, evJoin;
    cudaEventCreateWithFlags(&evFork, cudaEventDisableTiming);
    cudaEventCreateWithFlags(&evJoin, cudaEventDisableTiming);

    cudaEventRecord(evFork, 0);
    cudaStreamWaitEvent(s2, evFork, 0);

    // side chain: cumsum(V) -> out
    k4a_partials<<<dim3(Bc, NCH), Hc*Dc, 0, s2>>>(V);
    k4c_cumsum<<<dim3(Bc, NCH), Hc*Dc, 0, s2>>>(V, out);
    cudaEventRecord(evJoin, s2);

    // main chain: build -> scores -> topk -> attention
    b_prep<<<64, 256>>>(IDXRAW);
    b_scan<<<NKR, 512>>>();
    b_fill<<<(Lc + 255)/256, 256>>>();
    k1_scores<<<dim3(NKR, BHc), 1024, K1_SMEM>>>(Q, K);
    k2_topk<<<BHc, 512>>>();
    k3_attn<<<dim3(NSPLIT, BHc), 512>>>(Q, K, V);

    // join: k5 needs both k3 (g_pacc) and k4c (out)
    cudaStreamWaitEvent(0, evJoin, 0);
    k5_combine_scatter<<<dim3(Uc, BHc), Dc>>>(out);
}

// round 16
// speedup vs baseline: 1.6221x; 1.0176x over previous
#include <cuda_runtime.h>
#include <math_constants.h>

#define Bc 8
#define Lc 4096
#define Hc 8
#define Dc 64
#define Sc 45
#define Uc 45
#define BHc (Bc*Hc)
#define NSPLIT 16
#define KSPLIT (Lc/NSPLIT)
#define TK 64
#define NCH 64
#define CHL (Lc/NCH)
#define KR 256
#define NKR (Lc/KR)            // 16
#define ETOT (Lc*Sc)
#define K1_SMEM (KR*Dc*4)      // 64 KB
#define FIXSCALE 16777216.0f

// ---- scratch ----
__device__ int   g_idx[ETOT];
__device__ int   g_cnt[NKR*Lc];
__device__ int   g_qofs[NKR*Lc];      // ABSOLUTE offsets (after b_base fixup)
__device__ int   g_krtot[NKR];        // entries per krange
__device__ int   g_krbase[NKR+1];     // global exclusive prefix of krtot
__device__ unsigned int g_pack[ETOT]; // (q<<8)|kl, sorted by (krange,q,s)
__device__ unsigned int g_Mmax[BHc*Lc];
__device__ unsigned long long g_Msum[BHc*Lc];
__device__ int   g_top[BHc*Uc];
__device__ float g_pm[BHc*Uc*NSPLIT];
__device__ float g_pl[BHc*Uc*NSPLIT];
__device__ float g_pacc[BHc*Uc*NSPLIT*Dc];
__device__ float g_ps[Bc*NCH*Hc*Dc];

// ============================================================
// b_prep: dtype detect + convert + per-krange counts + zero accums
// ============================================================
__global__ void __launch_bounds__(256) b_prep(const void* __restrict__ raw)
{
    __shared__ unsigned int red[256];
    const unsigned int* p = (const unsigned int*)raw;
    unsigned int acc = 0;
    for (int j = 1 + 2*threadIdx.x; j < 1024; j += 512) acc |= p[j];
    red[threadIdx.x] = acc;
    __syncthreads();
    for (int o = 128; o > 0; o >>= 1) {
        if (threadIdx.x < o) red[threadIdx.x] |= red[threadIdx.x + o];
        __syncthreads();
    }
    int mode64 = (red[0] == 0u) ? 1 : 0;

    int nthr = gridDim.x * 256;
    int gt = blockIdx.x*256 + threadIdx.x;
    for (int i = gt; i < BHc*Lc; i += nthr) {
        g_Mmax[i] = 0u;
        g_Msum[i] = 0ull;
    }

    int q = gt;
    if (q >= Lc) return;
    int c[NKR];
    #pragma unroll
    for (int i = 0; i < NKR; i++) c[i] = 0;
    for (int s = 0; s < Sc; s++) {
        int v;
        if (mode64) v = (int)((const long long*)raw)[q*Sc + s];
        else        v = ((const int*)raw)[q*Sc + s];
        g_idx[q*Sc + s] = v;
        c[v >> 8]++;
    }
    #pragma unroll
    for (int i = 0; i < NKR; i++) g_cnt[i*Lc + q] = c[i];
}

// ============================================================
// b_scan: block per krange; RELATIVE exclusive scan + total.
// ============================================================
__global__ void __launch_bounds__(512) b_scan()
{
    __shared__ int part[512];
    int kr = blockIdx.x, t = threadIdx.x;
    int v[8], pre[8], sum = 0;
    for (int j = 0; j < 8; j++) {
        v[j] = g_cnt[kr*Lc + t*8 + j];
        pre[j] = sum; sum += v[j];
    }
    part[t] = sum;
    __syncthreads();
    for (int off = 1; off < 512; off <<= 1) {
        int x = (t >= off) ? part[t-off] : 0;
        __syncthreads();
        part[t] += x;
        __syncthreads();
    }
    int excl = part[t] - sum;
    for (int j = 0; j < 8; j++)
        g_qofs[kr*Lc + t*8 + j] = excl + pre[j];
    if (t == 511) g_krtot[kr] = part[511];
}

// b_base: single warp computes global prefix of krtot
__global__ void b_base()
{
    if (threadIdx.x == 0) {
        int acc = 0;
        #pragma unroll
        for (int i = 0; i < NKR; i++) { g_krbase[i] = acc; acc += g_krtot[i]; }
        g_krbase[NKR] = acc;
    }
}

// ============================================================
// b_fill: thread per q; absolute cursors = relative + krbase.
// ============================================================
__global__ void __launch_bounds__(256) b_fill()
{
    int q = blockIdx.x * 256 + threadIdx.x;
    if (q >= Lc) return;
    int cur[NKR];
    #pragma unroll
    for (int i = 0; i < NKR; i++) cur[i] = g_qofs[i*Lc + q] + g_krbase[i];
    unsigned int qb = (unsigned int)q << 8;
    for (int s = 0; s < Sc; s++) {
        int k = g_idx[q*Sc + s];
        int kr = k >> 8;
        g_pack[cur[kr]++] = qb | ((unsigned int)k & 255u);
    }
}

// ============================================================
// K1 (banked, R13/R14 inner loop): key-tiled scoring,
// conflict-free {t,t+8} parts, per-q-run atomics. 2 blocks/SM.
// ============================================================
__global__ void __launch_bounds__(1024) k1_scores(
    const float* __restrict__ Q, const float* __restrict__ K)
{
    extern __shared__ float4 Ks4[];   // [KR][16] = 64KB
    int kr = blockIdx.x, bh = blockIdx.y;
    int b = bh >> 3, h = bh & 7;
    int tid = threadIdx.x;
    const float4* Q4 = (const float4*)Q;
    const float4* K4 = (const float4*)K;

    int kb = kr * KR;
    for (int i = tid; i < KR*16; i += 1024) {
        int row = i >> 4, part = i & 15;
        Ks4[i] = K4[(((b*Lc + kb + row)*Hc + h) << 4) + part];
    }
    __syncthreads();

    int start = g_krbase[kr];
    int end   = g_krbase[kr+1];
    int n = end - start;
    int gid = tid >> 3, t = tid & 7;
    int per = (n + 127) >> 7;
    int e0 = gid * per;
    int e1 = min(n, e0 + per);
    const int qrow_base = ((b*Lc*Hc + h) << 4) + t;   // parts t and t+8
    const int mbase = bh * Lc;
    const unsigned int* __restrict__ pk = g_pack + start;

    int qcur = -1;
    float runMax = -CUDART_INF_F, runSum = 0.f;
    float4 qa = make_float4(0.f,0.f,0.f,0.f), qb = qa;

    #pragma unroll 4
    for (int e = e0; e < e1; e++) {
        unsigned int en = pk[e];
        int q = (int)(en >> 8);
        if (q != qcur) {
            if (t == 0 && qcur >= 0) {
                unsigned int u = __float_as_uint(runMax);
                unsigned int key = (u & 0x80000000u) ? ~u : (u | 0x80000000u);
                atomicMax(&g_Mmax[mbase + qcur], key);
                atomicAdd(&g_Msum[mbase + qcur],
                          (unsigned long long)(long long)__float2ll_rn(runSum * FIXSCALE));
            }
            qcur = q;
            runMax = -CUDART_INF_F; runSum = 0.f;
            const float4* qp = &Q4[qrow_base + (q << 7)];
            qa = __ldg(qp); qb = __ldg(qp + 8);
        }
        int ki = (int)((en & 255u) << 4) + t;
        float4 ka = Ks4[ki], kc = Ks4[ki + 8];
        float d = qa.x*ka.x + qa.y*ka.y + qa.z*ka.z + qa.w*ka.w
                + qb.x*kc.x + qb.y*kc.y + qb.z*kc.z + qb.w*kc.w;
        d += __shfl_xor_sync(0xffffffffu, d, 1, 8);
        d += __shfl_xor_sync(0xffffffffu, d, 2, 8);
        d += __shfl_xor_sync(0xffffffffu, d, 4, 8);
        runMax = fmaxf(runMax, d);
        runSum += d;
    }
    if (t == 0 && qcur >= 0) {
        unsigned int u = __float_as_uint(runMax);
        unsigned int key = (u & 0x80000000u) ? ~u : (u | 0x80000000u);
        atomicMax(&g_Mmax[mbase + qcur], key);
        atomicAdd(&g_Msum[mbase + qcur],
                  (unsigned long long)(long long)__float2ll_rn(runSum * FIXSCALE));
    }
}

// ============================================================
// K2: M from (max,sum) + radix top-45, 512 threads
// ============================================================
__global__ void __launch_bounds__(512) k2_topk()
{
    __shared__ unsigned int keys[Lc];
    __shared__ int hist[256];
    __shared__ int sel_bin, sel_rem, cnt;
    int bh = blockIdx.x, tid = threadIdx.x;
    for (int i = tid; i < Lc; i += 512) {
        unsigned int mk = g_Mmax[bh*Lc + i];
        unsigned int uu = (mk & 0x80000000u) ? (mk & 0x7FFFFFFFu) : ~mk;
        float mmax = __uint_as_float(uu);
        long long sll = (long long)g_Msum[bh*Lc + i];
        float M = mmax - (float)sll * (1.0f / (FIXSCALE * (float)Lc));
        unsigned int u = __float_as_uint(M);
        keys[i] = (u & 0x80000000u) ? ~u : (u | 0x80000000u);
    }
    if (tid == 0) cnt = 0;
    __syncthreads();
    unsigned int prefix = 0; int need = Uc;
    for (int shift = 24; shift >= 0; shift -= 8) {
        if (tid < 256) hist[tid] = 0;
        __syncthreads();
        for (int i = tid; i < Lc; i += 512) {
            unsigned int k = keys[i];
            if (shift == 24 || (k >> (shift+8)) == prefix)
                atomicAdd(&hist[(k >> shift) & 255], 1);
        }
        __syncthreads();
        for (int off = 1; off < 256; off <<= 1) {
            int v = (tid < 256 && tid + off < 256) ? hist[tid + off] : 0;
            __syncthreads();
            if (tid < 256) hist[tid] += v;
            __syncthreads();
        }
        if (tid < 256) {
            int S  = hist[tid];
            int Sn = (tid < 255) ? hist[tid + 1] : 0;
            if (S >= need && Sn < need) { sel_bin = tid; sel_rem = need - Sn; }
        }
        __syncthreads();
        prefix = (prefix << 8) | (unsigned int)sel_bin;
        need = sel_rem;
        __syncthreads();
    }
    for (int i = tid; i < Lc; i += 512) {
        if (keys[i] > prefix) { int p = atomicAdd(&cnt, 1); g_top[bh*Uc + p] = i; }
    }
    __syncthreads();
    for (int i = tid; i < Lc; i += 512) {
        if (keys[i] == prefix) {
            int p = atomicAdd(&cnt, 1);
            if (p < Uc) g_top[bh*Uc + p] = i;
        }
    }
}

// ============================================================
// K3: flash attention, joint 3-u per warp (shared LDS/shfl)
// ============================================================
__global__ void __launch_bounds__(512) k3_attn(
    const float* __restrict__ Q, const float* __restrict__ K,
    const float* __restrict__ V)
{
    __shared__ float Qs[Uc][Dc];
    __shared__ int   qpos_s[Uc];
    __shared__ float Kt[Dc][TK+1];
    __shared__ __align__(16) float Vt[TK][Dc];
    int split = blockIdx.x, bh = blockIdx.y;
    int b = bh >> 3, h = bh & 7;
    int tid = threadIdx.x, lane = tid & 31, w = tid >> 5;

    if (tid < Uc) qpos_s[tid] = g_top[bh*Uc + tid];
    __syncthreads();
    for (int i = tid; i < Uc*Dc; i += 512) {
        int u = i >> 6, d = i & 63;
        int qp = qpos_s[u];
        Qs[u][d] = Q[(((b*Lc + qp)*Hc + h) << 6) + d] * 0.125f;
    }
    __syncthreads();

    int maxqp = 0;
    for (int u = 0; u < Uc; u++) maxqp = max(maxqp, qpos_s[u]);
    int kb0 = split * KSPLIT;
    int ntiles = 0;
    if (maxqp >= kb0) {
        int nn = (maxqp - kb0) / TK + 1;
        ntiles = nn < (KSPLIT/TK) ? nn : (KSPLIT/TK);
    }

    int u0 = w*3;
    int qp[3]; bool val[3];
    #pragma unroll
    for (int j = 0; j < 3; j++) {
        int u = u0 + j;
        val[j] = (u < Uc);
        qp[j] = val[j] ? qpos_s[u] : -0x40000000;
    }
    int wqmax = max(qp[0], max(qp[1], qp[2]));

    float m[3], lsum[3], acc0[3], acc1[3];
    #pragma unroll
    for (int j = 0; j < 3; j++) { m[j] = -CUDART_INF_F; lsum[j]=0.f; acc0[j]=0.f; acc1[j]=0.f; }

    const float4* K4 = (const float4*)K;
    const float4* V4 = (const float4*)V;

    for (int tile = 0; tile < ntiles; tile++) {
        int kb = kb0 + tile * TK;
        for (int i = tid; i < TK*16; i += 512) {
            int k = i >> 4, d4 = i & 15;
            int gbase = (((b*Lc + kb + k)*Hc + h) << 4) + d4;
            float4 kv = K4[gbase];
            int d = d4 * 4;
            Kt[d][k] = kv.x; Kt[d+1][k] = kv.y; Kt[d+2][k] = kv.z; Kt[d+3][k] = kv.w;
            ((float4*)&Vt[k][0])[d4] = V4[gbase];
        }
        __syncthreads();
        if (wqmax >= kb) {
            float s0[3] = {0.f,0.f,0.f}, s1[3] = {0.f,0.f,0.f};
            #pragma unroll 8
            for (int d = 0; d < Dc; d++) {
                float kt0 = Kt[d][lane], kt1 = Kt[d][lane+32];
                #pragma unroll
                for (int j = 0; j < 3; j++) {
                    float qd = Qs[min(u0+j, Uc-1)][d];
                    s0[j] += qd * kt0;
                    s1[j] += qd * kt1;
                }
            }
            float p0[3], p1[3];
            int kmax = 0;
            #pragma unroll
            for (int j = 0; j < 3; j++) {
                if (val[j] && qp[j] >= kb) {
                    int nk = min(TK, qp[j] - kb + 1);
                    kmax = max(kmax, nk);
                    float t0 = (lane      < nk) ? s0[j] : -CUDART_INF_F;
                    float t1 = (lane + 32 < nk) ? s1[j] : -CUDART_INF_F;
                    float tm = fmaxf(t0, t1);
                    #pragma unroll
                    for (int o = 16; o > 0; o >>= 1) tm = fmaxf(tm, __shfl_xor_sync(0xffffffffu, tm, o));
                    float newm = fmaxf(m[j], tm);
                    p0[j] = __expf(t0 - newm);
                    p1[j] = __expf(t1 - newm);
                    float ps = p0[j] + p1[j];
                    #pragma unroll
                    for (int o = 16; o > 0; o >>= 1) ps += __shfl_xor_sync(0xffffffffu, ps, o);
                    float cf = __expf(m[j] - newm);
                    lsum[j] = lsum[j]*cf + ps;
                    m[j] = newm;
                    acc0[j] *= cf; acc1[j] *= cf;
                } else { p0[j] = 0.f; p1[j] = 0.f; }
            }
            int k1end = min(kmax, 32);
            for (int k = 0; k < k1end; k++) {
                float vt0 = Vt[k][lane], vt1 = Vt[k][lane+32];
                #pragma unroll
                for (int j = 0; j < 3; j++) {
                    float pk = __shfl_sync(0xffffffffu, p0[j], k);
                    acc0[j] += pk * vt0;
                    acc1[j] += pk * vt1;
                }
            }
            for (int k = 32; k < kmax; k++) {
                float vt0 = Vt[k][lane], vt1 = Vt[k][lane+32];
                #pragma unroll
                for (int j = 0; j < 3; j++) {
                    float pk = __shfl_sync(0xffffffffu, p1[j], k - 32);
                    acc0[j] += pk * vt0;
                    acc1[j] += pk * vt1;
                }
            }
        }
        __syncthreads();
    }

    #pragma unroll
    for (int j = 0; j < 3; j++) {
        if (!val[j]) continue;
        int base = ((bh*Uc + u0 + j))*NSPLIT + split;
        if (qp[j] < kb0) {
            if (lane == 0) { g_pm[base] = -CUDART_INF_F; g_pl[base] = 0.f; }
            g_pacc[base*Dc + lane] = 0.f;
            g_pacc[base*Dc + lane + 32] = 0.f;
        } else {
            if (lane == 0) { g_pm[base] = m[j]; g_pl[base] = lsum[j]; }
            g_pacc[base*Dc + lane] = acc0[j];
            g_pacc[base*Dc + lane + 32] = acc1[j];
        }
    }
}

// ============================================================
// K4a: per-chunk partial sums. K4c: self-computed prefix + cumsum.
// ============================================================
__global__ void __launch_bounds__(512) k4a_partials(const float* __restrict__ V)
{
    int b = blockIdx.x, ch = blockIdx.y, tid = threadIdx.x;
    float s = 0.f;
    int base = (b*Lc + ch*CHL) * (Hc*Dc) + tid;
    #pragma unroll 4
    for (int l = 0; l < CHL; l++) s += V[base + l*(Hc*Dc)];
    g_ps[(b*NCH + ch)*(Hc*Dc) + tid] = s;
}

__global__ void __launch_bounds__(512) k4c_cumsum(const float* __restrict__ V,
                                                  float* __restrict__ out)
{
    int b = blockIdx.x, ch = blockIdx.y, tid = threadIdx.x;
    float acc = 0.f;
    for (int i = 0; i < ch; i++)
        acc += g_ps[(b*NCH + i)*(Hc*Dc) + tid];
    int base = (b*Lc + ch*CHL) * (Hc*Dc) + tid;
    #pragma unroll 4
    for (int l = 0; l < CHL; l++) {
        acc += V[base + l*(Hc*Dc)];
        out[base + l*(Hc*Dc)] = acc;
    }
}

// K5: combine split-KV partials and scatter into output
__global__ void __launch_bounds__(64) k5_combine_scatter(float* __restrict__ out)
{
    int u = blockIdx.x, bh = blockIdx.y, d = threadIdx.x;
    int b = bh >> 3, h = bh & 7;
    int base = (bh*Uc + u)*NSPLIT;
    float pm[NSPLIT], pl[NSPLIT];
    float M = -CUDART_INF_F;
    #pragma unroll
    for (int s = 0; s < NSPLIT; s++) {
        pm[s] = g_pm[base+s]; pl[s] = g_pl[base+s];
        M = fmaxf(M, pm[s]);
    }
    float Ls = 0.f, r = 0.f;
    #pragma unroll
    for (int s = 0; s < NSPLIT; s++) {
        float e = __expf(pm[s] - M);
        Ls += pl[s] * e;
        r  += g_pacc[(base+s)*Dc + d] * e;
    }
    int qp = g_top[bh*Uc + u];
    out[(((b*Lc + qp)*Hc + h) << 6) + d] = r / Ls;
}

// ============================================================
extern "C" void kernel_launch(void* const* d_in, const int* in_sizes, int n_in,
                              void* d_out, int out_size)
{
    const float* Q = (const float*)d_in[0];
    const float* K = (const float*)d_in[1];
    const float* V = (const float*)d_in[2];
    const void*  IDXRAW = d_in[3];
    float* out = (float*)d_out;

    cudaFuncSetAttribute(k1_scores, cudaFuncAttributeMaxDynamicSharedMemorySize, K1_SMEM);

    // fork a side stream for the V-cumsum chain (independent of k1..k3)
    cudaStream_t s2;
    cudaStreamCreateWithFlags(&s2, cudaStreamNonBlocking);
    cudaEvent_t evFork, evJoin;
    cudaEventCreateWithFlags(&evFork, cudaEventDisableTiming);
    cudaEventCreateWithFlags(&evJoin, cudaEventDisableTiming);

    cudaEventRecord(evFork, 0);
    cudaStreamWaitEvent(s2, evFork, 0);

    // side chain: cumsum(V) -> out
    k4a_partials<<<dim3(Bc, NCH), Hc*Dc, 0, s2>>>(V);
    k4c_cumsum<<<dim3(Bc, NCH), Hc*Dc, 0, s2>>>(V, out);
    cudaEventRecord(evJoin, s2);

    // main chain: build -> scores -> topk -> attention
    b_prep<<<64, 256>>>(IDXRAW);
    b_scan<<<NKR, 512>>>();
    b_base<<<1, 32>>>();
    b_fill<<<(Lc + 255)/256, 256>>>();
    k1_scores<<<dim3(NKR, BHc), 1024, K1_SMEM>>>(Q, K);
    k2_topk<<<BHc, 512>>>();
    k3_attn<<<dim3(NSPLIT, BHc), 512>>>(Q, K, V);

    // join: k5 needs both k3 (g_pacc) and k4c (out)
    cudaStreamWaitEvent(0, evJoin, 0);
    k5_combine_scatter<<<dim3(Uc, BHc), Dc>>>(out);
}